// round 13
// baseline (speedup 1.0000x reference)
#include <cuda_runtime.h>

#define EMBED    1024
#define HEADS    16
#define HEAD_DIM 64
#define BATCH    4
#define SEQ      2048
#define M_TOT    (BATCH*SEQ)      // 8192 rows
#define BH       (BATCH*HEADS)    // 64 batch-heads
#define NQT      (SEQ/64)         // 32 q-tiles per bh

typedef unsigned long long u64;
typedef unsigned int u32;

// ---------------- packed f32x2 helpers (Blackwell FFMA2 path) --------------
__device__ __forceinline__ u64 pk2(float x, float y) {
    u64 r; asm("mov.b64 %0, {%1, %2};" : "=l"(r) : "f"(x), "f"(y)); return r;
}
__device__ __forceinline__ void upk2(float& x, float& y, u64 v) {
    asm("mov.b64 {%0, %1}, %2;" : "=f"(x), "=f"(y) : "l"(v));
}
__device__ __forceinline__ void ffma2(u64& d, u64 a, u64 b) {
    asm("fma.rn.f32x2 %0, %1, %2, %0;" : "+l"(d) : "l"(a), "l"(b));
}
__device__ __forceinline__ float hadd2(u64 v) {
    float x, y; upk2(x, y, v); return x + y;
}

// ---------------- tf32 helpers ---------------------------------------------
__device__ __forceinline__ u32 f2tf32(float x) {
    u32 r; asm("cvt.rna.tf32.f32 %0, %1;" : "=r"(r) : "f"(x)); return r;
}
__device__ __forceinline__ void mma_tf32(float* d, const u32* a, const u32* b) {
    asm volatile(
        "mma.sync.aligned.m16n8k8.row.col.f32.tf32.tf32.f32 "
        "{%0,%1,%2,%3}, {%4,%5,%6,%7}, {%8,%9}, {%0,%1,%2,%3};"
        : "+f"(d[0]), "+f"(d[1]), "+f"(d[2]), "+f"(d[3])
        : "r"(a[0]), "r"(a[1]), "r"(a[2]), "r"(a[3]), "r"(b[0]), "r"(b[1]));
}
__device__ __forceinline__ void cpa16(void* sdst, const void* gsrc) {
    u32 s = (u32)__cvta_generic_to_shared(sdst);
    asm volatile("cp.async.ca.shared.global [%0], [%1], 16;" :: "r"(s), "l"(gsrc));
}

// ---------------- scratch (device globals: allocation-free) ----------------
__device__ float g_q[BH * SEQ * HEAD_DIM];     // [b,h,s,d], pre-scaled by 1/sqrt(D)
__device__ float g_k[BH * SEQ * HEAD_DIM];     // [b,h,s,d]
__device__ float g_v[BH * SEQ * HEAD_DIM];     // [b,h,s,d]
__device__ float g_attn[M_TOT * EMBED];        // [b,s,e]

// ---------------- tf32 tensor-core GEMM-NT (unchanged from R10) -------------
#define GBM 128
#define GBN 128
#define GBK 16
#define GP  20
#define GNT (EMBED / GBK)

template<int MODE>
__global__ __launch_bounds__(256, 2) void sgemm_tf32(
    const float* __restrict__ A, const float* __restrict__ W,
    const float* __restrict__ bias, float* __restrict__ C, float scale)
{
    __shared__ float As[2][GBM][GP];
    __shared__ float Bs[2][GBN][GP];

    const int tid  = threadIdx.x;
    const int wid  = tid >> 5;
    const int lane = tid & 31;
    const int g    = lane >> 2;
    const int t4   = lane & 3;
    const int wm   = wid >> 2;
    const int wn   = wid & 3;
    const int m_base = wm * 64;
    const int n_base = wn * 32;

    const int row_blk = blockIdx.y * GBM;
    const int col_blk = blockIdx.x * GBN;

    const float* Ag = A + (size_t)row_blk * EMBED;
    const float* Bg = W + (size_t)col_blk * EMBED;

    const int cr = tid >> 2;
    const int cc = (tid & 3) * 4;

    float acc[4][4][4];
    #pragma unroll
    for (int mt = 0; mt < 4; mt++)
        #pragma unroll
        for (int nt = 0; nt < 4; nt++)
            #pragma unroll
            for (int r = 0; r < 4; r++) acc[mt][nt][r] = 0.f;

    {
        const float* ap = Ag + (size_t)cr * EMBED + cc;
        const float* bp = Bg + (size_t)cr * EMBED + cc;
        cpa16(&As[0][cr][cc],      ap);
        cpa16(&As[0][cr + 64][cc], ap + (size_t)64 * EMBED);
        cpa16(&Bs[0][cr][cc],      bp);
        cpa16(&Bs[0][cr + 64][cc], bp + (size_t)64 * EMBED);
        asm volatile("cp.async.commit_group;" ::: "memory");
    }

    for (int t = 0; t < GNT; t++) {
        const int s = t & 1;
        if (t + 1 < GNT) {
            const int sn = (t + 1) & 1;
            const float* ap = Ag + (size_t)cr * EMBED + (t + 1) * GBK + cc;
            const float* bp = Bg + (size_t)cr * EMBED + (t + 1) * GBK + cc;
            cpa16(&As[sn][cr][cc],      ap);
            cpa16(&As[sn][cr + 64][cc], ap + (size_t)64 * EMBED);
            cpa16(&Bs[sn][cr][cc],      bp);
            cpa16(&Bs[sn][cr + 64][cc], bp + (size_t)64 * EMBED);
            asm volatile("cp.async.commit_group;" ::: "memory");
            asm volatile("cp.async.wait_group 1;" ::: "memory");
        } else {
            asm volatile("cp.async.wait_group 0;" ::: "memory");
        }
        __syncthreads();

        #pragma unroll
        for (int kk = 0; kk < GBK; kk += 8) {
            u32 a[4][4], b[4][2];
            #pragma unroll
            for (int mt = 0; mt < 4; mt++) {
                const float* p = &As[s][m_base + mt*16 + g][kk + t4];
                a[mt][0] = f2tf32(p[0]);
                a[mt][1] = f2tf32(p[8 * GP]);
                a[mt][2] = f2tf32(p[4]);
                a[mt][3] = f2tf32(p[8 * GP + 4]);
            }
            #pragma unroll
            for (int nt = 0; nt < 4; nt++) {
                const float* p = &Bs[s][n_base + nt*8 + g][kk + t4];
                b[nt][0] = f2tf32(p[0]);
                b[nt][1] = f2tf32(p[4]);
            }
            #pragma unroll
            for (int mt = 0; mt < 4; mt++)
                #pragma unroll
                for (int nt = 0; nt < 4; nt++)
                    mma_tf32(acc[mt][nt], a[mt], b[nt]);
        }
        __syncthreads();
    }

    #pragma unroll
    for (int mt = 0; mt < 4; mt++) {
        #pragma unroll
        for (int nt = 0; nt < 4; nt++) {
            const int c0 = col_blk + n_base + nt*8 + 2*t4;
            const float bia0 = bias[c0], bia1 = bias[c0 + 1];
            #pragma unroll
            for (int half = 0; half < 2; half++) {
                const int r = row_blk + m_base + mt*16 + g + half*8;
                float v0 = acc[mt][nt][half*2 + 0] + bia0;
                float v1 = acc[mt][nt][half*2 + 1] + bia1;
                if (MODE == 0) {
                    v0 *= scale; v1 *= scale;
                    const int bb = r / SEQ, ss = r % SEQ;
                    const int h = c0 / HEAD_DIM, d = c0 % HEAD_DIM;
                    float* dst = &((float*)C)[(((size_t)(bb*HEADS + h))*SEQ + ss)*HEAD_DIM + d];
                    *(float2*)dst = make_float2(v0, v1);
                } else {
                    *(float2*)&C[(size_t)r * EMBED + c0] = make_float2(v0, v1);
                }
            }
        }
    }
}

// ---------------- Flash attention (causal), Br=Bc=64, D=64 -----------------
// Mirror-pair load balancing: block `pair` processes qt = NQT-1-pair (long,
// first) then qt = pair (short). Every block does exactly NQT+1 k-tiles.
// Inner loops identical to the measured-good R9/R10 version.
#define PADW 68
#define FA_SMEM (4 * 64 * PADW * (int)sizeof(float))   // 69632 B

__global__ __launch_bounds__(256) void flash_attn_kernel(
    const float* __restrict__ Q, const float* __restrict__ K,
    const float* __restrict__ V, float* __restrict__ Out)
{
    extern __shared__ float sm[];
    float (*Qs)[PADW] = (float(*)[PADW])(sm);
    float (*Ks)[PADW] = (float(*)[PADW])(sm + 64*PADW);
    float (*Vt)[PADW] = (float(*)[PADW])(sm + 2*64*PADW);   // [d][c] transposed
    float (*Ps)[PADW] = (float(*)[PADW])(sm + 3*64*PADW);

    const int bh   = blockIdx.y;
    const int pair = blockIdx.x;        // 0..NQT/2-1

    const float* Qb = Q + (size_t)bh * SEQ * HEAD_DIM;
    const float* Kb = K + (size_t)bh * SEQ * HEAD_DIM;
    const float* Vb = V + (size_t)bh * SEQ * HEAD_DIM;

    const int tid = threadIdx.x;
    const int tx = tid & 15;
    const int ty = tid >> 4;
    const int R0 = ty * 4;

    const int lrow = tid >> 4;          // 0..15
    const int lcol = (tid & 15) * 4;    // 0..60
    const int vd  = tid & 63;
    const int vcg = tid >> 6;

    const int b = bh / HEADS, h = bh % HEADS;

    #pragma unroll 1
    for (int pass = 0; pass < 2; pass++) {
        const int qt = pass ? pair : (NQT - 1 - pair);   // long tile first
        const int q0 = qt * 64;

        __syncthreads();   // Qs (and Ks/Vt/Ps) free from previous pass readers

        // load Q tile
        #pragma unroll
        for (int rr = 0; rr < 64; rr += 16) {
            float4 v = *(const float4*)(Qb + (size_t)(q0 + lrow + rr) * HEAD_DIM + lcol);
            *(float4*)&Qs[lrow + rr][lcol] = v;
        }

        float m_i[4], l_i[4], o[4][4];
        #pragma unroll
        for (int i = 0; i < 4; i++) {
            m_i[i] = -1e30f; l_i[i] = 0.f;
            #pragma unroll
            for (int j = 0; j < 4; j++) o[i][j] = 0.f;
        }

        for (int kt = 0; kt <= qt; kt++) {
            __syncthreads();   // protect Ks/Vt/Ps from previous iteration readers

            #pragma unroll
            for (int rr = 0; rr < 64; rr += 16) {
                const size_t gph = (size_t)(kt*64 + lrow + rr) * HEAD_DIM + lcol;
                *(float4*)&Ks[lrow + rr][lcol] = *(const float4*)(Kb + gph);
            }
            {
                const float* Vp = Vb + (size_t)(kt*64) * HEAD_DIM + vd;
                #pragma unroll
                for (int u = 0; u < 4; u++) {
                    const int c = vcg*16 + u*4;
                    float4 t;
                    t.x = Vp[(size_t)(c+0) * HEAD_DIM];
                    t.y = Vp[(size_t)(c+1) * HEAD_DIM];
                    t.z = Vp[(size_t)(c+2) * HEAD_DIM];
                    t.w = Vp[(size_t)(c+3) * HEAD_DIM];
                    *(float4*)&Vt[vd][c] = t;
                }
            }
            __syncthreads();

            // scores S = Q K^T, packed f32x2 over d
            u64 s2[4][4];
            #pragma unroll
            for (int i = 0; i < 4; i++)
                #pragma unroll
                for (int j = 0; j < 4; j++) s2[i][j] = 0ull;

            #pragma unroll 4
            for (int d0 = 0; d0 < 64; d0 += 4) {
                float4 qa[4], kb[4];
                #pragma unroll
                for (int i = 0; i < 4; i++) qa[i] = *(const float4*)&Qs[R0+i][d0];
                #pragma unroll
                for (int j = 0; j < 4; j++) kb[j] = *(const float4*)&Ks[tx + 16*j][d0];
                u64 qu[4][2], ku[4][2];
                #pragma unroll
                for (int i = 0; i < 4; i++) {
                    qu[i][0] = pk2(qa[i].x, qa[i].y);
                    qu[i][1] = pk2(qa[i].z, qa[i].w);
                }
                #pragma unroll
                for (int j = 0; j < 4; j++) {
                    ku[j][0] = pk2(kb[j].x, kb[j].y);
                    ku[j][1] = pk2(kb[j].z, kb[j].w);
                }
                #pragma unroll
                for (int i = 0; i < 4; i++)
                    #pragma unroll
                    for (int j = 0; j < 4; j++) {
                        ffma2(s2[i][j], qu[i][0], ku[j][0]);
                        ffma2(s2[i][j], qu[i][1], ku[j][1]);
                    }
            }

            float s[4][4];
            #pragma unroll
            for (int i = 0; i < 4; i++)
                #pragma unroll
                for (int j = 0; j < 4; j++) s[i][j] = hadd2(s2[i][j]);

            if (kt == qt) {
                #pragma unroll
                for (int i = 0; i < 4; i++)
                    #pragma unroll
                    for (int j = 0; j < 4; j++)
                        if (tx + 16*j > R0 + i) s[i][j] = -1e30f;
            }

            // online softmax
            #pragma unroll
            for (int i = 0; i < 4; i++) {
                float mx = s[i][0];
                #pragma unroll
                for (int j = 1; j < 4; j++) mx = fmaxf(mx, s[i][j]);
                #pragma unroll
                for (int off = 1; off < 16; off <<= 1)
                    mx = fmaxf(mx, __shfl_xor_sync(0xffffffffu, mx, off));
                const float mnew  = fmaxf(m_i[i], mx);
                const float alpha = __expf(m_i[i] - mnew);
                float rs = 0.f;
                #pragma unroll
                for (int j = 0; j < 4; j++) {
                    const float p = __expf(s[i][j] - mnew);
                    Ps[R0+i][tx + 16*j] = p;
                    rs += p;
                }
                #pragma unroll
                for (int off = 1; off < 16; off <<= 1)
                    rs += __shfl_xor_sync(0xffffffffu, rs, off);
                l_i[i] = l_i[i] * alpha + rs;
                m_i[i] = mnew;
                #pragma unroll
                for (int j = 0; j < 4; j++) o[i][j] *= alpha;
            }
            __syncthreads();

            // O += P @ V (packed over c, V transposed)
            u64 ot2[4][4];
            #pragma unroll
            for (int i = 0; i < 4; i++)
                #pragma unroll
                for (int j = 0; j < 4; j++) ot2[i][j] = 0ull;

            #pragma unroll 4
            for (int c0 = 0; c0 < 64; c0 += 4) {
                float4 pa[4], vb[4];
                #pragma unroll
                for (int i = 0; i < 4; i++) pa[i] = *(const float4*)&Ps[R0+i][c0];
                #pragma unroll
                for (int j = 0; j < 4; j++) vb[j] = *(const float4*)&Vt[tx + 16*j][c0];
                u64 pu[4][2], vu[4][2];
                #pragma unroll
                for (int i = 0; i < 4; i++) {
                    pu[i][0] = pk2(pa[i].x, pa[i].y);
                    pu[i][1] = pk2(pa[i].z, pa[i].w);
                }
                #pragma unroll
                for (int j = 0; j < 4; j++) {
                    vu[j][0] = pk2(vb[j].x, vb[j].y);
                    vu[j][1] = pk2(vb[j].z, vb[j].w);
                }
                #pragma unroll
                for (int i = 0; i < 4; i++)
                    #pragma unroll
                    for (int j = 0; j < 4; j++) {
                        ffma2(ot2[i][j], pu[i][0], vu[j][0]);
                        ffma2(ot2[i][j], pu[i][1], vu[j][1]);
                    }
            }
            #pragma unroll
            for (int i = 0; i < 4; i++)
                #pragma unroll
                for (int j = 0; j < 4; j++) o[i][j] += hadd2(ot2[i][j]);
        }

        // write back to [b, s, h*64 + (tx+16j)]
        #pragma unroll
        for (int i = 0; i < 4; i++) {
            const int srow = q0 + R0 + i;
            const float inv = 1.0f / l_i[i];
            #pragma unroll
            for (int j = 0; j < 4; j++)
                Out[((size_t)(b*SEQ + srow))*EMBED + h*HEAD_DIM + tx + 16*j] = o[i][j] * inv;
        }
    }
}

// ---------------------------------------------------------------------------
extern "C" void kernel_launch(void* const* d_in, const int* in_sizes, int n_in,
                              void* d_out, int out_size)
{
    const float* query  = (const float*)d_in[0];
    const float* key_in = (const float*)d_in[1];
    const float* value  = (const float*)d_in[2];
    // d_in[3] = causal mask (int32), known causal -> unused
    const float* Wq = (const float*)d_in[4];
    const float* bq = (const float*)d_in[5];
    const float* Wk = (const float*)d_in[6];
    const float* bk = (const float*)d_in[7];
    const float* Wv = (const float*)d_in[8];
    const float* bv = (const float*)d_in[9];
    const float* Wo = (const float*)d_in[10];
    const float* bo = (const float*)d_in[11];
    float* out = (float*)d_out;

    void *pq, *pk, *pv, *pa;
    cudaGetSymbolAddress(&pq, g_q);
    cudaGetSymbolAddress(&pk, g_k);
    cudaGetSymbolAddress(&pv, g_v);
    cudaGetSymbolAddress(&pa, g_attn);

    cudaFuncSetAttribute(flash_attn_kernel,
                         cudaFuncAttributeMaxDynamicSharedMemorySize, FA_SMEM);

    const dim3 gg(EMBED / GBN, M_TOT / GBM);   // (8, 64)
    const float qscale = 0.125f;               // 1/sqrt(HEAD_DIM)

    sgemm_tf32<0><<<gg, 256>>>(query,  Wq, bq, (float*)pq, qscale);
    sgemm_tf32<0><<<gg, 256>>>(key_in, Wk, bk, (float*)pk, 1.0f);
    sgemm_tf32<0><<<gg, 256>>>(value,  Wv, bv, (float*)pv, 1.0f);

    flash_attn_kernel<<<dim3(NQT/2, BH), 256, FA_SMEM>>>(
        (const float*)pq, (const float*)pk, (const float*)pv, (float*)pa);

    sgemm_tf32<1><<<gg, 256>>>((const float*)pa, Wo, bo, out, 1.0f);
}

// round 14
// speedup vs baseline: 1.3700x; 1.3700x over previous
#include <cuda_runtime.h>

#define EMBED    1024
#define HEADS    16
#define HEAD_DIM 64
#define BATCH    4
#define SEQ      2048
#define M_TOT    (BATCH*SEQ)      // 8192 rows
#define BH       (BATCH*HEADS)    // 64 batch-heads
#define NQT      (SEQ/64)         // 32 q-tiles per bh

typedef unsigned long long u64;
typedef unsigned int u32;

// ---------------- tf32 helpers (GEMM) ---------------------------------------
__device__ __forceinline__ u32 f2tf32(float x) {
    u32 r; asm("cvt.rna.tf32.f32 %0, %1;" : "=r"(r) : "f"(x)); return r;
}
__device__ __forceinline__ void mma_tf32(float* d, const u32* a, const u32* b) {
    asm volatile(
        "mma.sync.aligned.m16n8k8.row.col.f32.tf32.tf32.f32 "
        "{%0,%1,%2,%3}, {%4,%5,%6,%7}, {%8,%9}, {%0,%1,%2,%3};"
        : "+f"(d[0]), "+f"(d[1]), "+f"(d[2]), "+f"(d[3])
        : "r"(a[0]), "r"(a[1]), "r"(a[2]), "r"(a[3]), "r"(b[0]), "r"(b[1]));
}
__device__ __forceinline__ void cpa16(void* sdst, const void* gsrc) {
    u32 s = (u32)__cvta_generic_to_shared(sdst);
    asm volatile("cp.async.ca.shared.global [%0], [%1], 16;" :: "r"(s), "l"(gsrc));
}

// ---------------- bf16 / ldmatrix / mma helpers (flash) ---------------------
// word = {hi:bf16(vhi) | lo:bf16(vlo)}: PTX cvt first source -> upper half.
__device__ __forceinline__ u32 bfpack(float vhi, float vlo) {
    u32 r; asm("cvt.rn.bf16x2.f32 %0, %1, %2;" : "=r"(r) : "f"(vhi), "f"(vlo)); return r;
}
__device__ __forceinline__ void ldm_x4(u32* r, u32 saddr) {
    asm volatile("ldmatrix.sync.aligned.m8n8.x4.shared.b16 {%0,%1,%2,%3}, [%4];"
        : "=r"(r[0]), "=r"(r[1]), "=r"(r[2]), "=r"(r[3]) : "r"(saddr));
}
__device__ __forceinline__ void ldm_x4t(u32* r, u32 saddr) {
    asm volatile("ldmatrix.sync.aligned.m8n8.x4.trans.shared.b16 {%0,%1,%2,%3}, [%4];"
        : "=r"(r[0]), "=r"(r[1]), "=r"(r[2]), "=r"(r[3]) : "r"(saddr));
}
__device__ __forceinline__ void mma_bf16(float* d, const u32* a, const u32* b) {
    asm volatile(
        "mma.sync.aligned.m16n8k16.row.col.f32.bf16.bf16.f32 "
        "{%0,%1,%2,%3}, {%4,%5,%6,%7}, {%8,%9}, {%0,%1,%2,%3};"
        : "+f"(d[0]), "+f"(d[1]), "+f"(d[2]), "+f"(d[3])
        : "r"(a[0]), "r"(a[1]), "r"(a[2]), "r"(a[3]), "r"(b[0]), "r"(b[1]));
}

// ---------------- scratch (device globals: allocation-free) ----------------
// Q/K/V pre-split bf16 (hi,lo): u32 word = bf16x2 of adjacent dims {d+1|d}.
__device__ u32 g_qhi[BH * SEQ * 32];
__device__ u32 g_qlo[BH * SEQ * 32];
__device__ u32 g_khi[BH * SEQ * 32];
__device__ u32 g_klo[BH * SEQ * 32];
__device__ u32 g_vhi[BH * SEQ * 32];
__device__ u32 g_vlo[BH * SEQ * 32];
__device__ float g_attn[M_TOT * EMBED];        // [b,s,e]

// ---------------- tf32 tensor-core GEMM-NT ---------------------------------
// MODE 0: split-bf16 scatter into [b,h,s,dpair] hi/lo (QKV projections)
// MODE 1: plain row-major f32 (output projection)
#define GBM 128
#define GBN 128
#define GBK 16
#define GP  20
#define GNT (EMBED / GBK)

template<int MODE>
__global__ __launch_bounds__(256, 2) void sgemm_tf32(
    const float* __restrict__ A, const float* __restrict__ W,
    const float* __restrict__ bias,
    u32* __restrict__ Chi, u32* __restrict__ Clo,
    float* __restrict__ Cf, float scale)
{
    __shared__ float As[2][GBM][GP];
    __shared__ float Bs[2][GBN][GP];

    const int tid  = threadIdx.x;
    const int wid  = tid >> 5;
    const int lane = tid & 31;
    const int g    = lane >> 2;
    const int t4   = lane & 3;
    const int wm   = wid >> 2;
    const int wn   = wid & 3;
    const int m_base = wm * 64;
    const int n_base = wn * 32;

    const int row_blk = blockIdx.y * GBM;
    const int col_blk = blockIdx.x * GBN;

    const float* Ag = A + (size_t)row_blk * EMBED;
    const float* Bg = W + (size_t)col_blk * EMBED;

    const int cr = tid >> 2;
    const int cc = (tid & 3) * 4;

    float acc[4][4][4];
    #pragma unroll
    for (int mt = 0; mt < 4; mt++)
        #pragma unroll
        for (int nt = 0; nt < 4; nt++)
            #pragma unroll
            for (int r = 0; r < 4; r++) acc[mt][nt][r] = 0.f;

    {
        const float* ap = Ag + (size_t)cr * EMBED + cc;
        const float* bp = Bg + (size_t)cr * EMBED + cc;
        cpa16(&As[0][cr][cc],      ap);
        cpa16(&As[0][cr + 64][cc], ap + (size_t)64 * EMBED);
        cpa16(&Bs[0][cr][cc],      bp);
        cpa16(&Bs[0][cr + 64][cc], bp + (size_t)64 * EMBED);
        asm volatile("cp.async.commit_group;" ::: "memory");
    }

    for (int t = 0; t < GNT; t++) {
        const int s = t & 1;
        if (t + 1 < GNT) {
            const int sn = (t + 1) & 1;
            const float* ap = Ag + (size_t)cr * EMBED + (t + 1) * GBK + cc;
            const float* bp = Bg + (size_t)cr * EMBED + (t + 1) * GBK + cc;
            cpa16(&As[sn][cr][cc],      ap);
            cpa16(&As[sn][cr + 64][cc], ap + (size_t)64 * EMBED);
            cpa16(&Bs[sn][cr][cc],      bp);
            cpa16(&Bs[sn][cr + 64][cc], bp + (size_t)64 * EMBED);
            asm volatile("cp.async.commit_group;" ::: "memory");
            asm volatile("cp.async.wait_group 1;" ::: "memory");
        } else {
            asm volatile("cp.async.wait_group 0;" ::: "memory");
        }
        __syncthreads();

        #pragma unroll
        for (int kk = 0; kk < GBK; kk += 8) {
            u32 a[4][4], b[4][2];
            #pragma unroll
            for (int mt = 0; mt < 4; mt++) {
                const float* p = &As[s][m_base + mt*16 + g][kk + t4];
                a[mt][0] = f2tf32(p[0]);
                a[mt][1] = f2tf32(p[8 * GP]);
                a[mt][2] = f2tf32(p[4]);
                a[mt][3] = f2tf32(p[8 * GP + 4]);
            }
            #pragma unroll
            for (int nt = 0; nt < 4; nt++) {
                const float* p = &Bs[s][n_base + nt*8 + g][kk + t4];
                b[nt][0] = f2tf32(p[0]);
                b[nt][1] = f2tf32(p[4]);
            }
            #pragma unroll
            for (int mt = 0; mt < 4; mt++)
                #pragma unroll
                for (int nt = 0; nt < 4; nt++)
                    mma_tf32(acc[mt][nt], a[mt], b[nt]);
        }
        __syncthreads();
    }

    #pragma unroll
    for (int mt = 0; mt < 4; mt++) {
        #pragma unroll
        for (int nt = 0; nt < 4; nt++) {
            const int c0 = col_blk + n_base + nt*8 + 2*t4;   // even
            const float bia0 = bias[c0], bia1 = bias[c0 + 1];
            #pragma unroll
            for (int half = 0; half < 2; half++) {
                const int r = row_blk + m_base + mt*16 + g + half*8;
                float v0 = acc[mt][nt][half*2 + 0] + bia0;
                float v1 = acc[mt][nt][half*2 + 1] + bia1;
                if (MODE == 0) {
                    v0 *= scale; v1 *= scale;
                    u32 hp = bfpack(v1, v0);
                    float h0 = __uint_as_float(hp << 16);
                    float h1 = __uint_as_float(hp & 0xffff0000u);
                    u32 lp = bfpack(v1 - h1, v0 - h0);
                    const int bb = r / SEQ, ss = r % SEQ;
                    const int hh = c0 / HEAD_DIM, d = c0 % HEAD_DIM;
                    const size_t idx = (((size_t)(bb*HEADS + hh))*SEQ + ss)*32 + (d >> 1);
                    Chi[idx] = hp;
                    Clo[idx] = lp;
                } else {
                    *(float2*)&Cf[(size_t)r * EMBED + c0] = make_float2(v0, v1);
                }
            }
        }
    }
}

// ---------------- bf16 split-2 tensor-core flash attention ------------------
// Br=Bc=64, D=64. CTA = 128 thr (4 warps); warp w owns q-rows 16w..16w+15.
// m16n8k16 bf16; 3-term split (hh + hl + lh). P fragments stay in registers.
#define FPITCH 72                    // bf16 elems/row; 144B = conflict-free walk
#define TILE_B (64 * FPITCH * 2)     // 9216 B
#define SM_QH 0
#define SM_QL (1*TILE_B)
#define SM_KH (2*TILE_B)
#define SM_KL (3*TILE_B)
#define SM_VH (4*TILE_B)
#define SM_VL (5*TILE_B)
#define FA_SMEM (6*TILE_B)           // 55296 B

__global__ __launch_bounds__(128) void flash_attn_bf16(
    const u32* __restrict__ Qh, const u32* __restrict__ Ql,
    const u32* __restrict__ Kh, const u32* __restrict__ Kl,
    const u32* __restrict__ Vh, const u32* __restrict__ Vl,
    float* __restrict__ Out)
{
    extern __shared__ char smc[];
    const u32 smb = (u32)__cvta_generic_to_shared(smc);

    const int bh   = blockIdx.y;
    const int pair = blockIdx.x;
    const int tid  = threadIdx.x;
    const int wid  = tid >> 5;
    const int lane = tid & 31;
    const int g    = lane >> 2;
    const int t4   = lane & 3;
    const int b = bh / HEADS, h = bh % HEADS;

    // tile builders: thread -> (row 0..63, half 0..1), 4x16B per thread
    const int brow  = tid >> 1;
    const int bhalf = tid & 1;
    const u32 sm_row_off = (u32)(brow * 144 + bhalf * 64);
    const size_t g_row_off = (size_t)brow * 32 + bhalf * 16;

    // ldmatrix byte offsets (within a tile)
    // A (Q): row = lane&15, k-col = (lane>>4)*8 elems
    const u32 a_off  = (u32)(((lane & 15) * FPITCH + ((lane >> 4) << 3)) * 2);
    // B (K) x4 over k32: mat = lane>>3; row = lane&7; k-off = (mat&1)*8 + (mat>>1)*16
    const u32 kb_off = (u32)(((lane & 7) * FPITCH
                              + (((lane >> 3) & 1) << 3) + ((lane >> 4) << 4)) * 2);
    // B (V, trans) x4 over c32: row c = lane (0..31)
    const u32 vb_off = (u32)(lane * FPITCH * 2);

    const size_t bh_base = (size_t)bh * SEQ * 32;

    #pragma unroll 1
    for (int pass = 0; pass < 2; pass++) {
        const int qt = pass ? pair : (NQT - 1 - pair);   // long tile first
        const int q0 = qt * 64;

        __syncthreads();
        // build Q hi/lo tiles
        {
            const u32* sqh = Qh + bh_base + (size_t)q0*32 + g_row_off;
            const u32* sql = Ql + bh_base + (size_t)q0*32 + g_row_off;
            #pragma unroll
            for (int i = 0; i < 4; i++) {
                *(uint4*)(smc + SM_QH + sm_row_off + i*16) = *(const uint4*)(sqh + i*4);
                *(uint4*)(smc + SM_QL + sm_row_off + i*16) = *(const uint4*)(sql + i*4);
            }
        }
        __syncthreads();

        // Q fragments (registers, reused across k-tiles)
        u32 qfh[4][4], qfl[4][4];
        #pragma unroll
        for (int kc = 0; kc < 4; kc++) {
            const u32 off = (u32)(wid*16*144) + a_off + kc*32;
            ldm_x4(qfh[kc], smb + SM_QH + off);
            ldm_x4(qfl[kc], smb + SM_QL + off);
        }

        float m0 = -1e30f, m1 = -1e30f, l0 = 0.f, l1 = 0.f;
        float o[8][4];
        #pragma unroll
        for (int nt = 0; nt < 8; nt++)
            #pragma unroll
            for (int e = 0; e < 4; e++) o[nt][e] = 0.f;

        for (int kt = 0; kt <= qt; kt++) {
            __syncthreads();   // K/V tiles free from previous iteration readers
            {
                const size_t kbase = bh_base + (size_t)(kt*64)*32 + g_row_off;
                const u32* skh = Kh + kbase;  const u32* skl = Kl + kbase;
                const u32* svh = Vh + kbase;  const u32* svl = Vl + kbase;
                #pragma unroll
                for (int i = 0; i < 4; i++) {
                    *(uint4*)(smc + SM_KH + sm_row_off + i*16) = *(const uint4*)(skh + i*4);
                    *(uint4*)(smc + SM_KL + sm_row_off + i*16) = *(const uint4*)(skl + i*4);
                    *(uint4*)(smc + SM_VH + sm_row_off + i*16) = *(const uint4*)(svh + i*4);
                    *(uint4*)(smc + SM_VL + sm_row_off + i*16) = *(const uint4*)(svl + i*4);
                }
            }
            __syncthreads();

            // ---- S = Q K^T (3-term split) ----
            float s[8][4];
            #pragma unroll
            for (int nt = 0; nt < 8; nt++)
                #pragma unroll
                for (int e = 0; e < 4; e++) s[nt][e] = 0.f;

            #pragma unroll
            for (int nt = 0; nt < 8; nt++) {
                #pragma unroll
                for (int kcp = 0; kcp < 2; kcp++) {       // k32 double-chunks
                    const u32 off = (u32)(nt*8*144) + kb_off + kcp*64;
                    u32 kbh[4], kbl[4];
                    ldm_x4(kbh, smb + SM_KH + off);
                    ldm_x4(kbl, smb + SM_KL + off);
                    mma_bf16(s[nt], qfh[2*kcp],   kbh);
                    mma_bf16(s[nt], qfh[2*kcp],   kbl);
                    mma_bf16(s[nt], qfl[2*kcp],   kbh);
                    mma_bf16(s[nt], qfh[2*kcp+1], kbh + 2);
                    mma_bf16(s[nt], qfh[2*kcp+1], kbl + 2);
                    mma_bf16(s[nt], qfl[2*kcp+1], kbh + 2);
                }
            }

            // ---- causal mask (diagonal tile; local coords) ----
            if (kt == qt) {
                const int row0 = wid*16 + g;
                #pragma unroll
                for (int nt = 0; nt < 8; nt++) {
                    const int c0l = nt*8 + 2*t4;
                    if (c0l     > row0)     s[nt][0] = -1e30f;
                    if (c0l + 1 > row0)     s[nt][1] = -1e30f;
                    if (c0l     > row0 + 8) s[nt][2] = -1e30f;
                    if (c0l + 1 > row0 + 8) s[nt][3] = -1e30f;
                }
            }

            // ---- online softmax (rows g and g+8; quad shfl over t4) ----
            float mx0 = -1e30f, mx1 = -1e30f;
            #pragma unroll
            for (int nt = 0; nt < 8; nt++) {
                mx0 = fmaxf(mx0, fmaxf(s[nt][0], s[nt][1]));
                mx1 = fmaxf(mx1, fmaxf(s[nt][2], s[nt][3]));
            }
            mx0 = fmaxf(mx0, __shfl_xor_sync(0xffffffffu, mx0, 1));
            mx0 = fmaxf(mx0, __shfl_xor_sync(0xffffffffu, mx0, 2));
            mx1 = fmaxf(mx1, __shfl_xor_sync(0xffffffffu, mx1, 1));
            mx1 = fmaxf(mx1, __shfl_xor_sync(0xffffffffu, mx1, 2));
            const float mn0 = fmaxf(m0, mx0), mn1 = fmaxf(m1, mx1);
            const float al0 = __expf(m0 - mn0), al1 = __expf(m1 - mn1);

            u32 phi[8], plo[8], phi2[8], plo2[8];
            float sum0 = 0.f, sum1 = 0.f;
            #pragma unroll
            for (int nt = 0; nt < 8; nt++) {
                const float p00 = __expf(s[nt][0] - mn0);
                const float p01 = __expf(s[nt][1] - mn0);
                const float p10 = __expf(s[nt][2] - mn1);
                const float p11 = __expf(s[nt][3] - mn1);
                sum0 += p00 + p01;
                sum1 += p10 + p11;
                const u32 hp0 = bfpack(p01, p00);
                phi[nt] = hp0;
                plo[nt] = bfpack(p01 - __uint_as_float(hp0 & 0xffff0000u),
                                 p00 - __uint_as_float(hp0 << 16));
                const u32 hp1 = bfpack(p11, p10);
                phi2[nt] = hp1;
                plo2[nt] = bfpack(p11 - __uint_as_float(hp1 & 0xffff0000u),
                                  p10 - __uint_as_float(hp1 << 16));
            }
            sum0 += __shfl_xor_sync(0xffffffffu, sum0, 1);
            sum0 += __shfl_xor_sync(0xffffffffu, sum0, 2);
            sum1 += __shfl_xor_sync(0xffffffffu, sum1, 1);
            sum1 += __shfl_xor_sync(0xffffffffu, sum1, 2);
            l0 = l0 * al0 + sum0;
            l1 = l1 * al1 + sum1;
            m0 = mn0; m1 = mn1;
            #pragma unroll
            for (int nt = 0; nt < 8; nt++) {
                o[nt][0] *= al0; o[nt][1] *= al0;
                o[nt][2] *= al1; o[nt][3] *= al1;
            }

            // ---- O += P V (3-term split; P A-fragments from registers) ----
            #pragma unroll
            for (int nt = 0; nt < 8; nt++) {          // d tiles of 8
                #pragma unroll
                for (int kcp = 0; kcp < 2; kcp++) {   // c32 double-chunks
                    const u32 off = (u32)(kcp*32*144) + vb_off + nt*16;
                    u32 vbh[4], vbl[4];
                    ldm_x4t(vbh, smb + SM_VH + off);
                    ldm_x4t(vbl, smb + SM_VL + off);
                    const int kc0 = 2*kcp, kc1 = 2*kcp + 1;
                    u32 pah0[4] = {phi[2*kc0], phi2[2*kc0], phi[2*kc0+1], phi2[2*kc0+1]};
                    u32 pal0[4] = {plo[2*kc0], plo2[2*kc0], plo[2*kc0+1], plo2[2*kc0+1]};
                    mma_bf16(o[nt], pah0, vbh);
                    mma_bf16(o[nt], pah0, vbl);
                    mma_bf16(o[nt], pal0, vbh);
                    u32 pah1[4] = {phi[2*kc1], phi2[2*kc1], phi[2*kc1+1], phi2[2*kc1+1]};
                    u32 pal1[4] = {plo[2*kc1], plo2[2*kc1], plo[2*kc1+1], plo2[2*kc1+1]};
                    mma_bf16(o[nt], pah1, vbh + 2);
                    mma_bf16(o[nt], pah1, vbl + 2);
                    mma_bf16(o[nt], pal1, vbh + 2);
                }
            }
        }

        // ---- writeback: Out[b, q0+row, h*64 + d] ----
        const float i0 = 1.0f / l0, i1 = 1.0f / l1;
        const int r0 = q0 + wid*16 + g;
        #pragma unroll
        for (int nt = 0; nt < 8; nt++) {
            const int d = nt*8 + 2*t4;
            *(float2*)&Out[((size_t)(b*SEQ + r0    ))*EMBED + h*HEAD_DIM + d] =
                make_float2(o[nt][0]*i0, o[nt][1]*i0);
            *(float2*)&Out[((size_t)(b*SEQ + r0 + 8))*EMBED + h*HEAD_DIM + d] =
                make_float2(o[nt][2]*i1, o[nt][3]*i1);
        }
    }
}

// ---------------------------------------------------------------------------
extern "C" void kernel_launch(void* const* d_in, const int* in_sizes, int n_in,
                              void* d_out, int out_size)
{
    const float* query  = (const float*)d_in[0];
    const float* key_in = (const float*)d_in[1];
    const float* value  = (const float*)d_in[2];
    // d_in[3] = causal mask (int32), known causal -> unused
    const float* Wq = (const float*)d_in[4];
    const float* bq = (const float*)d_in[5];
    const float* Wk = (const float*)d_in[6];
    const float* bk = (const float*)d_in[7];
    const float* Wv = (const float*)d_in[8];
    const float* bv = (const float*)d_in[9];
    const float* Wo = (const float*)d_in[10];
    const float* bo = (const float*)d_in[11];
    float* out = (float*)d_out;

    void *pqh, *pql, *pkh, *pkl, *pvh, *pvl, *pa;
    cudaGetSymbolAddress(&pqh, g_qhi);
    cudaGetSymbolAddress(&pql, g_qlo);
    cudaGetSymbolAddress(&pkh, g_khi);
    cudaGetSymbolAddress(&pkl, g_klo);
    cudaGetSymbolAddress(&pvh, g_vhi);
    cudaGetSymbolAddress(&pvl, g_vlo);
    cudaGetSymbolAddress(&pa,  g_attn);

    cudaFuncSetAttribute(flash_attn_bf16,
                         cudaFuncAttributeMaxDynamicSharedMemorySize, FA_SMEM);

    const dim3 gg(EMBED / GBN, M_TOT / GBM);   // (8, 64)
    const float qscale = 0.125f;               // 1/sqrt(HEAD_DIM)

    sgemm_tf32<0><<<gg, 256>>>(query,  Wq, bq, (u32*)pqh, (u32*)pql, nullptr, qscale);
    sgemm_tf32<0><<<gg, 256>>>(key_in, Wk, bk, (u32*)pkh, (u32*)pkl, nullptr, 1.0f);
    sgemm_tf32<0><<<gg, 256>>>(value,  Wv, bv, (u32*)pvh, (u32*)pvl, nullptr, 1.0f);

    flash_attn_bf16<<<dim3(NQT/2, BH), 128, FA_SMEM>>>(
        (const u32*)pqh, (const u32*)pql, (const u32*)pkh, (const u32*)pkl,
        (const u32*)pvh, (const u32*)pvl, (float*)pa);

    sgemm_tf32<1><<<gg, 256>>>((const float*)pa, Wo, bo, nullptr, nullptr, out, 1.0f);
}

// round 15
// speedup vs baseline: 1.4363x; 1.0484x over previous
#include <cuda_runtime.h>

#define EMBED    1024
#define HEADS    16
#define HEAD_DIM 64
#define BATCH    4
#define SEQ      2048
#define M_TOT    (BATCH*SEQ)      // 8192 rows
#define BH       (BATCH*HEADS)    // 64 batch-heads
#define NQT      (SEQ/64)         // 32 q-tiles per bh

typedef unsigned long long u64;
typedef unsigned int u32;

// ---------------- tf32 helpers (GEMM) ---------------------------------------
__device__ __forceinline__ u32 f2tf32(float x) {
    u32 r; asm("cvt.rna.tf32.f32 %0, %1;" : "=r"(r) : "f"(x)); return r;
}
__device__ __forceinline__ void mma_tf32(float* d, const u32* a, const u32* b) {
    asm volatile(
        "mma.sync.aligned.m16n8k8.row.col.f32.tf32.tf32.f32 "
        "{%0,%1,%2,%3}, {%4,%5,%6,%7}, {%8,%9}, {%0,%1,%2,%3};"
        : "+f"(d[0]), "+f"(d[1]), "+f"(d[2]), "+f"(d[3])
        : "r"(a[0]), "r"(a[1]), "r"(a[2]), "r"(a[3]), "r"(b[0]), "r"(b[1]));
}
__device__ __forceinline__ void cpa16(void* sdst, const void* gsrc) {
    u32 s = (u32)__cvta_generic_to_shared(sdst);
    asm volatile("cp.async.ca.shared.global [%0], [%1], 16;" :: "r"(s), "l"(gsrc));
}

// ---------------- bf16 / ldmatrix / mma helpers (flash) ---------------------
// word = {hi:bf16(vhi) | lo:bf16(vlo)}: PTX cvt first source -> upper half.
__device__ __forceinline__ u32 bfpack(float vhi, float vlo) {
    u32 r; asm("cvt.rn.bf16x2.f32 %0, %1, %2;" : "=r"(r) : "f"(vhi), "f"(vlo)); return r;
}
__device__ __forceinline__ void ldm_x4(u32* r, u32 saddr) {
    asm volatile("ldmatrix.sync.aligned.m8n8.x4.shared.b16 {%0,%1,%2,%3}, [%4];"
        : "=r"(r[0]), "=r"(r[1]), "=r"(r[2]), "=r"(r[3]) : "r"(saddr));
}
__device__ __forceinline__ void ldm_x4t(u32* r, u32 saddr) {
    asm volatile("ldmatrix.sync.aligned.m8n8.x4.trans.shared.b16 {%0,%1,%2,%3}, [%4];"
        : "=r"(r[0]), "=r"(r[1]), "=r"(r[2]), "=r"(r[3]) : "r"(saddr));
}
__device__ __forceinline__ void mma_bf16(float* d, const u32* a, const u32* b) {
    asm volatile(
        "mma.sync.aligned.m16n8k16.row.col.f32.bf16.bf16.f32 "
        "{%0,%1,%2,%3}, {%4,%5,%6,%7}, {%8,%9}, {%0,%1,%2,%3};"
        : "+f"(d[0]), "+f"(d[1]), "+f"(d[2]), "+f"(d[3])
        : "r"(a[0]), "r"(a[1]), "r"(a[2]), "r"(a[3]), "r"(b[0]), "r"(b[1]));
}

// ---------------- scratch (device globals: allocation-free) ----------------
// Q/K/V pre-split bf16 (hi,lo): u32 word = bf16x2 of adjacent dims {d+1|d}.
__device__ u32 g_qhi[BH * SEQ * 32];
__device__ u32 g_qlo[BH * SEQ * 32];
__device__ u32 g_khi[BH * SEQ * 32];
__device__ u32 g_klo[BH * SEQ * 32];
__device__ u32 g_vhi[BH * SEQ * 32];
__device__ u32 g_vlo[BH * SEQ * 32];
__device__ float g_attn[M_TOT * EMBED];        // [b,s,e]

// ---------------- tf32 tensor-core GEMM-NT (unchanged from R14) -------------
#define GBM 128
#define GBN 128
#define GBK 16
#define GP  20
#define GNT (EMBED / GBK)

template<int MODE>
__global__ __launch_bounds__(256, 2) void sgemm_tf32(
    const float* __restrict__ A, const float* __restrict__ W,
    const float* __restrict__ bias,
    u32* __restrict__ Chi, u32* __restrict__ Clo,
    float* __restrict__ Cf, float scale)
{
    __shared__ float As[2][GBM][GP];
    __shared__ float Bs[2][GBN][GP];

    const int tid  = threadIdx.x;
    const int wid  = tid >> 5;
    const int lane = tid & 31;
    const int g    = lane >> 2;
    const int t4   = lane & 3;
    const int wm   = wid >> 2;
    const int wn   = wid & 3;
    const int m_base = wm * 64;
    const int n_base = wn * 32;

    const int row_blk = blockIdx.y * GBM;
    const int col_blk = blockIdx.x * GBN;

    const float* Ag = A + (size_t)row_blk * EMBED;
    const float* Bg = W + (size_t)col_blk * EMBED;

    const int cr = tid >> 2;
    const int cc = (tid & 3) * 4;

    float acc[4][4][4];
    #pragma unroll
    for (int mt = 0; mt < 4; mt++)
        #pragma unroll
        for (int nt = 0; nt < 4; nt++)
            #pragma unroll
            for (int r = 0; r < 4; r++) acc[mt][nt][r] = 0.f;

    {
        const float* ap = Ag + (size_t)cr * EMBED + cc;
        const float* bp = Bg + (size_t)cr * EMBED + cc;
        cpa16(&As[0][cr][cc],      ap);
        cpa16(&As[0][cr + 64][cc], ap + (size_t)64 * EMBED);
        cpa16(&Bs[0][cr][cc],      bp);
        cpa16(&Bs[0][cr + 64][cc], bp + (size_t)64 * EMBED);
        asm volatile("cp.async.commit_group;" ::: "memory");
    }

    for (int t = 0; t < GNT; t++) {
        const int s = t & 1;
        if (t + 1 < GNT) {
            const int sn = (t + 1) & 1;
            const float* ap = Ag + (size_t)cr * EMBED + (t + 1) * GBK + cc;
            const float* bp = Bg + (size_t)cr * EMBED + (t + 1) * GBK + cc;
            cpa16(&As[sn][cr][cc],      ap);
            cpa16(&As[sn][cr + 64][cc], ap + (size_t)64 * EMBED);
            cpa16(&Bs[sn][cr][cc],      bp);
            cpa16(&Bs[sn][cr + 64][cc], bp + (size_t)64 * EMBED);
            asm volatile("cp.async.commit_group;" ::: "memory");
            asm volatile("cp.async.wait_group 1;" ::: "memory");
        } else {
            asm volatile("cp.async.wait_group 0;" ::: "memory");
        }
        __syncthreads();

        #pragma unroll
        for (int kk = 0; kk < GBK; kk += 8) {
            u32 a[4][4], b[4][2];
            #pragma unroll
            for (int mt = 0; mt < 4; mt++) {
                const float* p = &As[s][m_base + mt*16 + g][kk + t4];
                a[mt][0] = f2tf32(p[0]);
                a[mt][1] = f2tf32(p[8 * GP]);
                a[mt][2] = f2tf32(p[4]);
                a[mt][3] = f2tf32(p[8 * GP + 4]);
            }
            #pragma unroll
            for (int nt = 0; nt < 4; nt++) {
                const float* p = &Bs[s][n_base + nt*8 + g][kk + t4];
                b[nt][0] = f2tf32(p[0]);
                b[nt][1] = f2tf32(p[4]);
            }
            #pragma unroll
            for (int mt = 0; mt < 4; mt++)
                #pragma unroll
                for (int nt = 0; nt < 4; nt++)
                    mma_tf32(acc[mt][nt], a[mt], b[nt]);
        }
        __syncthreads();
    }

    #pragma unroll
    for (int mt = 0; mt < 4; mt++) {
        #pragma unroll
        for (int nt = 0; nt < 4; nt++) {
            const int c0 = col_blk + n_base + nt*8 + 2*t4;   // even
            const float bia0 = bias[c0], bia1 = bias[c0 + 1];
            #pragma unroll
            for (int half = 0; half < 2; half++) {
                const int r = row_blk + m_base + mt*16 + g + half*8;
                float v0 = acc[mt][nt][half*2 + 0] + bia0;
                float v1 = acc[mt][nt][half*2 + 1] + bia1;
                if (MODE == 0) {
                    v0 *= scale; v1 *= scale;
                    u32 hp = bfpack(v1, v0);
                    float h0 = __uint_as_float(hp << 16);
                    float h1 = __uint_as_float(hp & 0xffff0000u);
                    u32 lp = bfpack(v1 - h1, v0 - h0);
                    const int bb = r / SEQ, ss = r % SEQ;
                    const int hh = c0 / HEAD_DIM, d = c0 % HEAD_DIM;
                    const size_t idx = (((size_t)(bb*HEADS + hh))*SEQ + ss)*32 + (d >> 1);
                    Chi[idx] = hp;
                    Clo[idx] = lp;
                } else {
                    *(float2*)&Cf[(size_t)r * EMBED + c0] = make_float2(v0, v1);
                }
            }
        }
    }
}

// ---------------- bf16 split-2 tensor-core flash attention ------------------
// Br=Bc=64, D=64. CTA = 128 thr (4 warps); warp w owns q-rows 16w..16w+15.
// m16n8k16 bf16; 3-term split (hh + hl + lh). P fragments stay in registers.
// K/V hi/lo tiles are a 2-stage cp.async ring: load(kt+1) overlaps compute(kt).
#define FPITCH 72                    // bf16 elems/row; 144B = conflict-free walk
#define TILE_B (64 * FPITCH * 2)     // 9216 B
#define SM_QH 0
#define SM_QL (1*TILE_B)
#define SM_KV (2*TILE_B)             // ring base
#define KV_STRIDE (4*TILE_B)         // per stage: KH,KL,VH,VL
#define FA_SMEM (2*TILE_B + 2*KV_STRIDE)   // 92160 B

__global__ __launch_bounds__(128) void flash_attn_bf16(
    const u32* __restrict__ Qh, const u32* __restrict__ Ql,
    const u32* __restrict__ Kh, const u32* __restrict__ Kl,
    const u32* __restrict__ Vh, const u32* __restrict__ Vl,
    float* __restrict__ Out)
{
    extern __shared__ char smc[];
    const u32 smb = (u32)__cvta_generic_to_shared(smc);

    const int bh   = blockIdx.y;
    const int pair = blockIdx.x;
    const int tid  = threadIdx.x;
    const int wid  = tid >> 5;
    const int lane = tid & 31;
    const int g    = lane >> 2;
    const int t4   = lane & 3;
    const int b = bh / HEADS, h = bh % HEADS;

    // tile builders: thread -> (row 0..63, half 0..1), 4x16B per thread
    const int brow  = tid >> 1;
    const int bhalf = tid & 1;
    const u32 sm_row_off = (u32)(brow * 144 + bhalf * 64);
    const size_t g_row_off = (size_t)brow * 32 + bhalf * 16;

    // ldmatrix byte offsets (within a tile)
    const u32 a_off  = (u32)(((lane & 15) * FPITCH + ((lane >> 4) << 3)) * 2);
    const u32 kb_off = (u32)(((lane & 7) * FPITCH
                              + (((lane >> 3) & 1) << 3) + ((lane >> 4) << 4)) * 2);
    const u32 vb_off = (u32)(lane * FPITCH * 2);

    const size_t bh_base = (size_t)bh * SEQ * 32;

    // issue cp.async loads of K/V hi/lo tiles for k-tile kt into stage s
    auto issue_kv = [&](int kt, int s) {
        const size_t kbase = bh_base + (size_t)(kt*64)*32 + g_row_off;
        char* dst = smc + SM_KV + s*KV_STRIDE;
        const u32* skh = Kh + kbase;  const u32* skl = Kl + kbase;
        const u32* svh = Vh + kbase;  const u32* svl = Vl + kbase;
        #pragma unroll
        for (int i = 0; i < 4; i++) {
            cpa16(dst + 0*TILE_B + sm_row_off + i*16, skh + i*4);
            cpa16(dst + 1*TILE_B + sm_row_off + i*16, skl + i*4);
            cpa16(dst + 2*TILE_B + sm_row_off + i*16, svh + i*4);
            cpa16(dst + 3*TILE_B + sm_row_off + i*16, svl + i*4);
        }
        asm volatile("cp.async.commit_group;" ::: "memory");
    };

    #pragma unroll 1
    for (int pass = 0; pass < 2; pass++) {
        const int qt = pass ? pair : (NQT - 1 - pair);   // long tile first
        const int q0 = qt * 64;

        __syncthreads();   // all buffers free from previous pass readers

        // build Q hi/lo tiles (sync stores) + kick off kt=0 K/V loads
        {
            const u32* sqh = Qh + bh_base + (size_t)q0*32 + g_row_off;
            const u32* sql = Ql + bh_base + (size_t)q0*32 + g_row_off;
            #pragma unroll
            for (int i = 0; i < 4; i++) {
                *(uint4*)(smc + SM_QH + sm_row_off + i*16) = *(const uint4*)(sqh + i*4);
                *(uint4*)(smc + SM_QL + sm_row_off + i*16) = *(const uint4*)(sql + i*4);
            }
        }
        issue_kv(0, 0);
        __syncthreads();   // Q tile visible

        // Q fragments (registers, reused across k-tiles)
        u32 qfh[4][4], qfl[4][4];
        #pragma unroll
        for (int kc = 0; kc < 4; kc++) {
            const u32 off = (u32)(wid*16*144) + a_off + kc*32;
            ldm_x4(qfh[kc], smb + SM_QH + off);
            ldm_x4(qfl[kc], smb + SM_QL + off);
        }

        float m0 = -1e30f, m1 = -1e30f, l0 = 0.f, l1 = 0.f;
        float o[8][4];
        #pragma unroll
        for (int nt = 0; nt < 8; nt++)
            #pragma unroll
            for (int e = 0; e < 4; e++) o[nt][e] = 0.f;

        for (int kt = 0; kt <= qt; kt++) {
            const int s = kt & 1;
            // wait for stage s data (the only pending group), then make it
            // visible to all threads; after this sync, everyone is also done
            // reading stage s^1, so it is safe to overwrite it.
            asm volatile("cp.async.wait_group 0;" ::: "memory");
            __syncthreads();
            if (kt < qt) issue_kv(kt + 1, s ^ 1);

            const u32 kvb = smb + SM_KV + (u32)(s * KV_STRIDE);
            const u32 kh_b = kvb,            kl_b = kvb + TILE_B;
            const u32 vh_b = kvb + 2*TILE_B, vl_b = kvb + 3*TILE_B;

            // ---- S = Q K^T (3-term split) ----
            float sacc[8][4];
            #pragma unroll
            for (int nt = 0; nt < 8; nt++)
                #pragma unroll
                for (int e = 0; e < 4; e++) sacc[nt][e] = 0.f;

            #pragma unroll
            for (int nt = 0; nt < 8; nt++) {
                #pragma unroll
                for (int kcp = 0; kcp < 2; kcp++) {       // k32 double-chunks
                    const u32 off = (u32)(nt*8*144) + kb_off + kcp*64;
                    u32 kbh[4], kbl[4];
                    ldm_x4(kbh, kh_b + off);
                    ldm_x4(kbl, kl_b + off);
                    mma_bf16(sacc[nt], qfh[2*kcp],   kbh);
                    mma_bf16(sacc[nt], qfh[2*kcp],   kbl);
                    mma_bf16(sacc[nt], qfl[2*kcp],   kbh);
                    mma_bf16(sacc[nt], qfh[2*kcp+1], kbh + 2);
                    mma_bf16(sacc[nt], qfh[2*kcp+1], kbl + 2);
                    mma_bf16(sacc[nt], qfl[2*kcp+1], kbh + 2);
                }
            }

            // ---- causal mask (diagonal tile; local coords) ----
            if (kt == qt) {
                const int row0 = wid*16 + g;
                #pragma unroll
                for (int nt = 0; nt < 8; nt++) {
                    const int c0l = nt*8 + 2*t4;
                    if (c0l     > row0)     sacc[nt][0] = -1e30f;
                    if (c0l + 1 > row0)     sacc[nt][1] = -1e30f;
                    if (c0l     > row0 + 8) sacc[nt][2] = -1e30f;
                    if (c0l + 1 > row0 + 8) sacc[nt][3] = -1e30f;
                }
            }

            // ---- online softmax (rows g and g+8; quad shfl over t4) ----
            float mx0 = -1e30f, mx1 = -1e30f;
            #pragma unroll
            for (int nt = 0; nt < 8; nt++) {
                mx0 = fmaxf(mx0, fmaxf(sacc[nt][0], sacc[nt][1]));
                mx1 = fmaxf(mx1, fmaxf(sacc[nt][2], sacc[nt][3]));
            }
            mx0 = fmaxf(mx0, __shfl_xor_sync(0xffffffffu, mx0, 1));
            mx0 = fmaxf(mx0, __shfl_xor_sync(0xffffffffu, mx0, 2));
            mx1 = fmaxf(mx1, __shfl_xor_sync(0xffffffffu, mx1, 1));
            mx1 = fmaxf(mx1, __shfl_xor_sync(0xffffffffu, mx1, 2));
            const float mn0 = fmaxf(m0, mx0), mn1 = fmaxf(m1, mx1);
            const float al0 = __expf(m0 - mn0), al1 = __expf(m1 - mn1);

            u32 phi[8], plo[8], phi2[8], plo2[8];
            float sum0 = 0.f, sum1 = 0.f;
            #pragma unroll
            for (int nt = 0; nt < 8; nt++) {
                const float p00 = __expf(sacc[nt][0] - mn0);
                const float p01 = __expf(sacc[nt][1] - mn0);
                const float p10 = __expf(sacc[nt][2] - mn1);
                const float p11 = __expf(sacc[nt][3] - mn1);
                sum0 += p00 + p01;
                sum1 += p10 + p11;
                const u32 hp0 = bfpack(p01, p00);
                phi[nt] = hp0;
                plo[nt] = bfpack(p01 - __uint_as_float(hp0 & 0xffff0000u),
                                 p00 - __uint_as_float(hp0 << 16));
                const u32 hp1 = bfpack(p11, p10);
                phi2[nt] = hp1;
                plo2[nt] = bfpack(p11 - __uint_as_float(hp1 & 0xffff0000u),
                                  p10 - __uint_as_float(hp1 << 16));
            }
            sum0 += __shfl_xor_sync(0xffffffffu, sum0, 1);
            sum0 += __shfl_xor_sync(0xffffffffu, sum0, 2);
            sum1 += __shfl_xor_sync(0xffffffffu, sum1, 1);
            sum1 += __shfl_xor_sync(0xffffffffu, sum1, 2);
            l0 = l0 * al0 + sum0;
            l1 = l1 * al1 + sum1;
            m0 = mn0; m1 = mn1;
            #pragma unroll
            for (int nt = 0; nt < 8; nt++) {
                o[nt][0] *= al0; o[nt][1] *= al0;
                o[nt][2] *= al1; o[nt][3] *= al1;
            }

            // ---- O += P V (3-term split; P A-fragments from registers) ----
            #pragma unroll
            for (int nt = 0; nt < 8; nt++) {          // d tiles of 8
                #pragma unroll
                for (int kcp = 0; kcp < 2; kcp++) {   // c32 double-chunks
                    const u32 off = (u32)(kcp*32*144) + vb_off + nt*16;
                    u32 vbh[4], vbl[4];
                    ldm_x4t(vbh, vh_b + off);
                    ldm_x4t(vbl, vl_b + off);
                    const int kc0 = 2*kcp, kc1 = 2*kcp + 1;
                    u32 pah0[4] = {phi[2*kc0], phi2[2*kc0], phi[2*kc0+1], phi2[2*kc0+1]};
                    u32 pal0[4] = {plo[2*kc0], plo2[2*kc0], plo[2*kc0+1], plo2[2*kc0+1]};
                    mma_bf16(o[nt], pah0, vbh);
                    mma_bf16(o[nt], pah0, vbl);
                    mma_bf16(o[nt], pal0, vbh);
                    u32 pah1[4] = {phi[2*kc1], phi2[2*kc1], phi[2*kc1+1], phi2[2*kc1+1]};
                    u32 pal1[4] = {plo[2*kc1], plo2[2*kc1], plo[2*kc1+1], plo2[2*kc1+1]};
                    mma_bf16(o[nt], pah1, vbh + 2);
                    mma_bf16(o[nt], pah1, vbl + 2);
                    mma_bf16(o[nt], pal1, vbh + 2);
                }
            }
        }

        // ---- writeback: Out[b, q0+row, h*64 + d] ----
        const float i0 = 1.0f / l0, i1 = 1.0f / l1;
        const int r0 = q0 + wid*16 + g;
        #pragma unroll
        for (int nt = 0; nt < 8; nt++) {
            const int d = nt*8 + 2*t4;
            *(float2*)&Out[((size_t)(b*SEQ + r0    ))*EMBED + h*HEAD_DIM + d] =
                make_float2(o[nt][0]*i0, o[nt][1]*i0);
            *(float2*)&Out[((size_t)(b*SEQ + r0 + 8))*EMBED + h*HEAD_DIM + d] =
                make_float2(o[nt][2]*i1, o[nt][3]*i1);
        }
    }
}

// ---------------------------------------------------------------------------
extern "C" void kernel_launch(void* const* d_in, const int* in_sizes, int n_in,
                              void* d_out, int out_size)
{
    const float* query  = (const float*)d_in[0];
    const float* key_in = (const float*)d_in[1];
    const float* value  = (const float*)d_in[2];
    // d_in[3] = causal mask (int32), known causal -> unused
    const float* Wq = (const float*)d_in[4];
    const float* bq = (const float*)d_in[5];
    const float* Wk = (const float*)d_in[6];
    const float* bk = (const float*)d_in[7];
    const float* Wv = (const float*)d_in[8];
    const float* bv = (const float*)d_in[9];
    const float* Wo = (const float*)d_in[10];
    const float* bo = (const float*)d_in[11];
    float* out = (float*)d_out;

    void *pqh, *pql, *pkh, *pkl, *pvh, *pvl, *pa;
    cudaGetSymbolAddress(&pqh, g_qhi);
    cudaGetSymbolAddress(&pql, g_qlo);
    cudaGetSymbolAddress(&pkh, g_khi);
    cudaGetSymbolAddress(&pkl, g_klo);
    cudaGetSymbolAddress(&pvh, g_vhi);
    cudaGetSymbolAddress(&pvl, g_vlo);
    cudaGetSymbolAddress(&pa,  g_attn);

    cudaFuncSetAttribute(flash_attn_bf16,
                         cudaFuncAttributeMaxDynamicSharedMemorySize, FA_SMEM);

    const dim3 gg(EMBED / GBN, M_TOT / GBM);   // (8, 64)
    const float qscale = 0.125f;               // 1/sqrt(HEAD_DIM)

    sgemm_tf32<0><<<gg, 256>>>(query,  Wq, bq, (u32*)pqh, (u32*)pql, nullptr, qscale);
    sgemm_tf32<0><<<gg, 256>>>(key_in, Wk, bk, (u32*)pkh, (u32*)pkl, nullptr, 1.0f);
    sgemm_tf32<0><<<gg, 256>>>(value,  Wv, bv, (u32*)pvh, (u32*)pvl, nullptr, 1.0f);

    flash_attn_bf16<<<dim3(NQT/2, BH), 128, FA_SMEM>>>(
        (const u32*)pqh, (const u32*)pql, (const u32*)pkh, (const u32*)pkl,
        (const u32*)pvh, (const u32*)pvl, (float*)pa);

    sgemm_tf32<1><<<gg, 256>>>((const float*)pa, Wo, bo, nullptr, nullptr, out, 1.0f);
}

// round 16
// speedup vs baseline: 1.4656x; 1.0204x over previous
#include <cuda_runtime.h>

#define EMBED    1024
#define HEADS    16
#define HEAD_DIM 64
#define BATCH    4
#define SEQ      2048
#define M_TOT    (BATCH*SEQ)      // 8192 rows
#define BH       (BATCH*HEADS)    // 64 batch-heads
#define NQT      (SEQ/64)         // 32 q-tiles per bh

typedef unsigned long long u64;
typedef unsigned int u32;

// ---------------- tf32 helpers (GEMM) ---------------------------------------
__device__ __forceinline__ u32 f2tf32(float x) {
    u32 r; asm("cvt.rna.tf32.f32 %0, %1;" : "=r"(r) : "f"(x)); return r;
}
__device__ __forceinline__ void mma_tf32(float* d, const u32* a, const u32* b) {
    asm volatile(
        "mma.sync.aligned.m16n8k8.row.col.f32.tf32.tf32.f32 "
        "{%0,%1,%2,%3}, {%4,%5,%6,%7}, {%8,%9}, {%0,%1,%2,%3};"
        : "+f"(d[0]), "+f"(d[1]), "+f"(d[2]), "+f"(d[3])
        : "r"(a[0]), "r"(a[1]), "r"(a[2]), "r"(a[3]), "r"(b[0]), "r"(b[1]));
}
__device__ __forceinline__ void cpa16(void* sdst, const void* gsrc) {
    u32 s = (u32)__cvta_generic_to_shared(sdst);
    asm volatile("cp.async.ca.shared.global [%0], [%1], 16;" :: "r"(s), "l"(gsrc));
}

// ---------------- bf16 / ldmatrix / mma helpers (flash) ---------------------
// word = {hi:bf16(vhi) | lo:bf16(vlo)}: PTX cvt first source -> upper half.
__device__ __forceinline__ u32 bfpack(float vhi, float vlo) {
    u32 r; asm("cvt.rn.bf16x2.f32 %0, %1, %2;" : "=r"(r) : "f"(vhi), "f"(vlo)); return r;
}
__device__ __forceinline__ void ldm_x4(u32* r, u32 saddr) {
    asm volatile("ldmatrix.sync.aligned.m8n8.x4.shared.b16 {%0,%1,%2,%3}, [%4];"
        : "=r"(r[0]), "=r"(r[1]), "=r"(r[2]), "=r"(r[3]) : "r"(saddr));
}
__device__ __forceinline__ void ldm_x4t(u32* r, u32 saddr) {
    asm volatile("ldmatrix.sync.aligned.m8n8.x4.trans.shared.b16 {%0,%1,%2,%3}, [%4];"
        : "=r"(r[0]), "=r"(r[1]), "=r"(r[2]), "=r"(r[3]) : "r"(saddr));
}
__device__ __forceinline__ void mma_bf16(float* d, const u32* a, const u32* b) {
    asm volatile(
        "mma.sync.aligned.m16n8k16.row.col.f32.bf16.bf16.f32 "
        "{%0,%1,%2,%3}, {%4,%5,%6,%7}, {%8,%9}, {%0,%1,%2,%3};"
        : "+f"(d[0]), "+f"(d[1]), "+f"(d[2]), "+f"(d[3])
        : "r"(a[0]), "r"(a[1]), "r"(a[2]), "r"(a[3]), "r"(b[0]), "r"(b[1]));
}

// ---------------- scratch (device globals: allocation-free) ----------------
// Q/K/V pre-split bf16 (hi,lo): u32 word = bf16x2 of adjacent dims {d+1|d}.
__device__ u32 g_qhi[BH * SEQ * 32];
__device__ u32 g_qlo[BH * SEQ * 32];
__device__ u32 g_khi[BH * SEQ * 32];
__device__ u32 g_klo[BH * SEQ * 32];
__device__ u32 g_vhi[BH * SEQ * 32];
__device__ u32 g_vlo[BH * SEQ * 32];
__device__ float g_attn[M_TOT * EMBED];        // [b,s,e]

// ---------------- tf32 tensor-core GEMM-NT (unchanged) ----------------------
#define GBM 128
#define GBN 128
#define GBK 16
#define GP  20
#define GNT (EMBED / GBK)

template<int MODE>
__global__ __launch_bounds__(256, 2) void sgemm_tf32(
    const float* __restrict__ A, const float* __restrict__ W,
    const float* __restrict__ bias,
    u32* __restrict__ Chi, u32* __restrict__ Clo,
    float* __restrict__ Cf, float scale)
{
    __shared__ float As[2][GBM][GP];
    __shared__ float Bs[2][GBN][GP];

    const int tid  = threadIdx.x;
    const int wid  = tid >> 5;
    const int lane = tid & 31;
    const int g    = lane >> 2;
    const int t4   = lane & 3;
    const int wm   = wid >> 2;
    const int wn   = wid & 3;
    const int m_base = wm * 64;
    const int n_base = wn * 32;

    const int row_blk = blockIdx.y * GBM;
    const int col_blk = blockIdx.x * GBN;

    const float* Ag = A + (size_t)row_blk * EMBED;
    const float* Bg = W + (size_t)col_blk * EMBED;

    const int cr = tid >> 2;
    const int cc = (tid & 3) * 4;

    float acc[4][4][4];
    #pragma unroll
    for (int mt = 0; mt < 4; mt++)
        #pragma unroll
        for (int nt = 0; nt < 4; nt++)
            #pragma unroll
            for (int r = 0; r < 4; r++) acc[mt][nt][r] = 0.f;

    {
        const float* ap = Ag + (size_t)cr * EMBED + cc;
        const float* bp = Bg + (size_t)cr * EMBED + cc;
        cpa16(&As[0][cr][cc],      ap);
        cpa16(&As[0][cr + 64][cc], ap + (size_t)64 * EMBED);
        cpa16(&Bs[0][cr][cc],      bp);
        cpa16(&Bs[0][cr + 64][cc], bp + (size_t)64 * EMBED);
        asm volatile("cp.async.commit_group;" ::: "memory");
    }

    for (int t = 0; t < GNT; t++) {
        const int s = t & 1;
        if (t + 1 < GNT) {
            const int sn = (t + 1) & 1;
            const float* ap = Ag + (size_t)cr * EMBED + (t + 1) * GBK + cc;
            const float* bp = Bg + (size_t)cr * EMBED + (t + 1) * GBK + cc;
            cpa16(&As[sn][cr][cc],      ap);
            cpa16(&As[sn][cr + 64][cc], ap + (size_t)64 * EMBED);
            cpa16(&Bs[sn][cr][cc],      bp);
            cpa16(&Bs[sn][cr + 64][cc], bp + (size_t)64 * EMBED);
            asm volatile("cp.async.commit_group;" ::: "memory");
            asm volatile("cp.async.wait_group 1;" ::: "memory");
        } else {
            asm volatile("cp.async.wait_group 0;" ::: "memory");
        }
        __syncthreads();

        #pragma unroll
        for (int kk = 0; kk < GBK; kk += 8) {
            u32 a[4][4], b[4][2];
            #pragma unroll
            for (int mt = 0; mt < 4; mt++) {
                const float* p = &As[s][m_base + mt*16 + g][kk + t4];
                a[mt][0] = f2tf32(p[0]);
                a[mt][1] = f2tf32(p[8 * GP]);
                a[mt][2] = f2tf32(p[4]);
                a[mt][3] = f2tf32(p[8 * GP + 4]);
            }
            #pragma unroll
            for (int nt = 0; nt < 4; nt++) {
                const float* p = &Bs[s][n_base + nt*8 + g][kk + t4];
                b[nt][0] = f2tf32(p[0]);
                b[nt][1] = f2tf32(p[4]);
            }
            #pragma unroll
            for (int mt = 0; mt < 4; mt++)
                #pragma unroll
                for (int nt = 0; nt < 4; nt++)
                    mma_tf32(acc[mt][nt], a[mt], b[nt]);
        }
        __syncthreads();
    }

    #pragma unroll
    for (int mt = 0; mt < 4; mt++) {
        #pragma unroll
        for (int nt = 0; nt < 4; nt++) {
            const int c0 = col_blk + n_base + nt*8 + 2*t4;   // even
            const float bia0 = bias[c0], bia1 = bias[c0 + 1];
            #pragma unroll
            for (int half = 0; half < 2; half++) {
                const int r = row_blk + m_base + mt*16 + g + half*8;
                float v0 = acc[mt][nt][half*2 + 0] + bia0;
                float v1 = acc[mt][nt][half*2 + 1] + bia1;
                if (MODE == 0) {
                    v0 *= scale; v1 *= scale;
                    u32 hp = bfpack(v1, v0);
                    float h0 = __uint_as_float(hp << 16);
                    float h1 = __uint_as_float(hp & 0xffff0000u);
                    u32 lp = bfpack(v1 - h1, v0 - h0);
                    const int bb = r / SEQ, ss = r % SEQ;
                    const int hh = c0 / HEAD_DIM, d = c0 % HEAD_DIM;
                    const size_t idx = (((size_t)(bb*HEADS + hh))*SEQ + ss)*32 + (d >> 1);
                    Chi[idx] = hp;
                    Clo[idx] = lp;
                } else {
                    *(float2*)&Cf[(size_t)r * EMBED + c0] = make_float2(v0, v1);
                }
            }
        }
    }
}

// ---------------- bf16 split-2 tensor-core flash attention ------------------
// Br=Bc=64, D=64. CTA = 128 thr (4 warps); warp w owns q-rows 16w..16w+15.
// m16n8k16 bf16; 3-term split (hh + hl + lh). P fragments stay in registers.
// K/V hi/lo tiles are a 2-stage cp.async ring: load(kt+1) overlaps compute(kt).
// Carveout forced to 100% so TWO CTAs fit per SM (2 x 92160B < 228KB).
#define FPITCH 72                    // bf16 elems/row; 144B = conflict-free walk
#define TILE_B (64 * FPITCH * 2)     // 9216 B
#define SM_QH 0
#define SM_QL (1*TILE_B)
#define SM_KV (2*TILE_B)             // ring base
#define KV_STRIDE (4*TILE_B)         // per stage: KH,KL,VH,VL
#define FA_SMEM (2*TILE_B + 2*KV_STRIDE)   // 92160 B

__global__ __launch_bounds__(128, 2) void flash_attn_bf16(
    const u32* __restrict__ Qh, const u32* __restrict__ Ql,
    const u32* __restrict__ Kh, const u32* __restrict__ Kl,
    const u32* __restrict__ Vh, const u32* __restrict__ Vl,
    float* __restrict__ Out)
{
    extern __shared__ char smc[];
    const u32 smb = (u32)__cvta_generic_to_shared(smc);

    const int bh   = blockIdx.y;
    const int pair = blockIdx.x;
    const int tid  = threadIdx.x;
    const int wid  = tid >> 5;
    const int lane = tid & 31;
    const int g    = lane >> 2;
    const int t4   = lane & 3;
    const int b = bh / HEADS, h = bh % HEADS;

    // tile builders: thread -> (row 0..63, half 0..1), 4x16B per thread
    const int brow  = tid >> 1;
    const int bhalf = tid & 1;
    const u32 sm_row_off = (u32)(brow * 144 + bhalf * 64);
    const size_t g_row_off = (size_t)brow * 32 + bhalf * 16;

    // ldmatrix byte offsets (within a tile)
    const u32 a_off  = (u32)(((lane & 15) * FPITCH + ((lane >> 4) << 3)) * 2);
    const u32 kb_off = (u32)(((lane & 7) * FPITCH
                              + (((lane >> 3) & 1) << 3) + ((lane >> 4) << 4)) * 2);
    const u32 vb_off = (u32)(lane * FPITCH * 2);

    const size_t bh_base = (size_t)bh * SEQ * 32;

    // issue cp.async loads of K/V hi/lo tiles for k-tile kt into stage s
    auto issue_kv = [&](int kt, int s) {
        const size_t kbase = bh_base + (size_t)(kt*64)*32 + g_row_off;
        char* dst = smc + SM_KV + s*KV_STRIDE;
        const u32* skh = Kh + kbase;  const u32* skl = Kl + kbase;
        const u32* svh = Vh + kbase;  const u32* svl = Vl + kbase;
        #pragma unroll
        for (int i = 0; i < 4; i++) {
            cpa16(dst + 0*TILE_B + sm_row_off + i*16, skh + i*4);
            cpa16(dst + 1*TILE_B + sm_row_off + i*16, skl + i*4);
            cpa16(dst + 2*TILE_B + sm_row_off + i*16, svh + i*4);
            cpa16(dst + 3*TILE_B + sm_row_off + i*16, svl + i*4);
        }
        asm volatile("cp.async.commit_group;" ::: "memory");
    };

    #pragma unroll 1
    for (int pass = 0; pass < 2; pass++) {
        const int qt = pass ? pair : (NQT - 1 - pair);   // long tile first
        const int q0 = qt * 64;

        __syncthreads();   // all buffers free from previous pass readers

        // build Q hi/lo tiles (sync stores) + kick off kt=0 K/V loads
        {
            const u32* sqh = Qh + bh_base + (size_t)q0*32 + g_row_off;
            const u32* sql = Ql + bh_base + (size_t)q0*32 + g_row_off;
            #pragma unroll
            for (int i = 0; i < 4; i++) {
                *(uint4*)(smc + SM_QH + sm_row_off + i*16) = *(const uint4*)(sqh + i*4);
                *(uint4*)(smc + SM_QL + sm_row_off + i*16) = *(const uint4*)(sql + i*4);
            }
        }
        issue_kv(0, 0);
        __syncthreads();   // Q tile visible

        // Q fragments (registers, reused across k-tiles)
        u32 qfh[4][4], qfl[4][4];
        #pragma unroll
        for (int kc = 0; kc < 4; kc++) {
            const u32 off = (u32)(wid*16*144) + a_off + kc*32;
            ldm_x4(qfh[kc], smb + SM_QH + off);
            ldm_x4(qfl[kc], smb + SM_QL + off);
        }

        float m0 = -1e30f, m1 = -1e30f, l0 = 0.f, l1 = 0.f;
        float o[8][4];
        #pragma unroll
        for (int nt = 0; nt < 8; nt++)
            #pragma unroll
            for (int e = 0; e < 4; e++) o[nt][e] = 0.f;

        for (int kt = 0; kt <= qt; kt++) {
            const int s = kt & 1;
            // wait for stage s data (the only pending group), then make it
            // visible; after this sync everyone is also done reading s^1.
            asm volatile("cp.async.wait_group 0;" ::: "memory");
            __syncthreads();
            if (kt < qt) issue_kv(kt + 1, s ^ 1);

            const u32 kvb = smb + SM_KV + (u32)(s * KV_STRIDE);
            const u32 kh_b = kvb,            kl_b = kvb + TILE_B;
            const u32 vh_b = kvb + 2*TILE_B, vl_b = kvb + 3*TILE_B;

            // ---- S = Q K^T (3-term split) ----
            float sacc[8][4];
            #pragma unroll
            for (int nt = 0; nt < 8; nt++)
                #pragma unroll
                for (int e = 0; e < 4; e++) sacc[nt][e] = 0.f;

            #pragma unroll
            for (int nt = 0; nt < 8; nt++) {
                #pragma unroll
                for (int kcp = 0; kcp < 2; kcp++) {       // k32 double-chunks
                    const u32 off = (u32)(nt*8*144) + kb_off + kcp*64;
                    u32 kbh[4], kbl[4];
                    ldm_x4(kbh, kh_b + off);
                    ldm_x4(kbl, kl_b + off);
                    mma_bf16(sacc[nt], qfh[2*kcp],   kbh);
                    mma_bf16(sacc[nt], qfh[2*kcp],   kbl);
                    mma_bf16(sacc[nt], qfl[2*kcp],   kbh);
                    mma_bf16(sacc[nt], qfh[2*kcp+1], kbh + 2);
                    mma_bf16(sacc[nt], qfh[2*kcp+1], kbl + 2);
                    mma_bf16(sacc[nt], qfl[2*kcp+1], kbh + 2);
                }
            }

            // ---- causal mask (diagonal tile; local coords) ----
            if (kt == qt) {
                const int row0 = wid*16 + g;
                #pragma unroll
                for (int nt = 0; nt < 8; nt++) {
                    const int c0l = nt*8 + 2*t4;
                    if (c0l     > row0)     sacc[nt][0] = -1e30f;
                    if (c0l + 1 > row0)     sacc[nt][1] = -1e30f;
                    if (c0l     > row0 + 8) sacc[nt][2] = -1e30f;
                    if (c0l + 1 > row0 + 8) sacc[nt][3] = -1e30f;
                }
            }

            // ---- online softmax (rows g and g+8; quad shfl over t4) ----
            float mx0 = -1e30f, mx1 = -1e30f;
            #pragma unroll
            for (int nt = 0; nt < 8; nt++) {
                mx0 = fmaxf(mx0, fmaxf(sacc[nt][0], sacc[nt][1]));
                mx1 = fmaxf(mx1, fmaxf(sacc[nt][2], sacc[nt][3]));
            }
            mx0 = fmaxf(mx0, __shfl_xor_sync(0xffffffffu, mx0, 1));
            mx0 = fmaxf(mx0, __shfl_xor_sync(0xffffffffu, mx0, 2));
            mx1 = fmaxf(mx1, __shfl_xor_sync(0xffffffffu, mx1, 1));
            mx1 = fmaxf(mx1, __shfl_xor_sync(0xffffffffu, mx1, 2));
            const float mn0 = fmaxf(m0, mx0), mn1 = fmaxf(m1, mx1);
            const float al0 = __expf(m0 - mn0), al1 = __expf(m1 - mn1);

            u32 phi[8], plo[8], phi2[8], plo2[8];
            float sum0 = 0.f, sum1 = 0.f;
            #pragma unroll
            for (int nt = 0; nt < 8; nt++) {
                const float p00 = __expf(sacc[nt][0] - mn0);
                const float p01 = __expf(sacc[nt][1] - mn0);
                const float p10 = __expf(sacc[nt][2] - mn1);
                const float p11 = __expf(sacc[nt][3] - mn1);
                sum0 += p00 + p01;
                sum1 += p10 + p11;
                const u32 hp0 = bfpack(p01, p00);
                phi[nt] = hp0;
                plo[nt] = bfpack(p01 - __uint_as_float(hp0 & 0xffff0000u),
                                 p00 - __uint_as_float(hp0 << 16));
                const u32 hp1 = bfpack(p11, p10);
                phi2[nt] = hp1;
                plo2[nt] = bfpack(p11 - __uint_as_float(hp1 & 0xffff0000u),
                                  p10 - __uint_as_float(hp1 << 16));
            }
            sum0 += __shfl_xor_sync(0xffffffffu, sum0, 1);
            sum0 += __shfl_xor_sync(0xffffffffu, sum0, 2);
            sum1 += __shfl_xor_sync(0xffffffffu, sum1, 1);
            sum1 += __shfl_xor_sync(0xffffffffu, sum1, 2);
            l0 = l0 * al0 + sum0;
            l1 = l1 * al1 + sum1;
            m0 = mn0; m1 = mn1;
            #pragma unroll
            for (int nt = 0; nt < 8; nt++) {
                o[nt][0] *= al0; o[nt][1] *= al0;
                o[nt][2] *= al1; o[nt][3] *= al1;
            }

            // ---- O += P V (3-term split; P A-fragments from registers) ----
            #pragma unroll
            for (int nt = 0; nt < 8; nt++) {          // d tiles of 8
                #pragma unroll
                for (int kcp = 0; kcp < 2; kcp++) {   // c32 double-chunks
                    const u32 off = (u32)(kcp*32*144) + vb_off + nt*16;
                    u32 vbh[4], vbl[4];
                    ldm_x4t(vbh, vh_b + off);
                    ldm_x4t(vbl, vl_b + off);
                    const int kc0 = 2*kcp, kc1 = 2*kcp + 1;
                    u32 pah0[4] = {phi[2*kc0], phi2[2*kc0], phi[2*kc0+1], phi2[2*kc0+1]};
                    u32 pal0[4] = {plo[2*kc0], plo2[2*kc0], plo[2*kc0+1], plo2[2*kc0+1]};
                    mma_bf16(o[nt], pah0, vbh);
                    mma_bf16(o[nt], pah0, vbl);
                    mma_bf16(o[nt], pal0, vbh);
                    u32 pah1[4] = {phi[2*kc1], phi2[2*kc1], phi[2*kc1+1], phi2[2*kc1+1]};
                    u32 pal1[4] = {plo[2*kc1], plo2[2*kc1], plo[2*kc1+1], plo2[2*kc1+1]};
                    mma_bf16(o[nt], pah1, vbh + 2);
                    mma_bf16(o[nt], pah1, vbl + 2);
                    mma_bf16(o[nt], pal1, vbh + 2);
                }
            }
        }

        // ---- writeback: Out[b, q0+row, h*64 + d] ----
        const float i0 = 1.0f / l0, i1 = 1.0f / l1;
        const int r0 = q0 + wid*16 + g;
        #pragma unroll
        for (int nt = 0; nt < 8; nt++) {
            const int d = nt*8 + 2*t4;
            *(float2*)&Out[((size_t)(b*SEQ + r0    ))*EMBED + h*HEAD_DIM + d] =
                make_float2(o[nt][0]*i0, o[nt][1]*i0);
            *(float2*)&Out[((size_t)(b*SEQ + r0 + 8))*EMBED + h*HEAD_DIM + d] =
                make_float2(o[nt][2]*i1, o[nt][3]*i1);
        }
    }
}

// ---------------------------------------------------------------------------
extern "C" void kernel_launch(void* const* d_in, const int* in_sizes, int n_in,
                              void* d_out, int out_size)
{
    const float* query  = (const float*)d_in[0];
    const float* key_in = (const float*)d_in[1];
    const float* value  = (const float*)d_in[2];
    // d_in[3] = causal mask (int32), known causal -> unused
    const float* Wq = (const float*)d_in[4];
    const float* bq = (const float*)d_in[5];
    const float* Wk = (const float*)d_in[6];
    const float* bk = (const float*)d_in[7];
    const float* Wv = (const float*)d_in[8];
    const float* bv = (const float*)d_in[9];
    const float* Wo = (const float*)d_in[10];
    const float* bo = (const float*)d_in[11];
    float* out = (float*)d_out;

    void *pqh, *pql, *pkh, *pkl, *pvh, *pvl, *pa;
    cudaGetSymbolAddress(&pqh, g_qhi);
    cudaGetSymbolAddress(&pql, g_qlo);
    cudaGetSymbolAddress(&pkh, g_khi);
    cudaGetSymbolAddress(&pkl, g_klo);
    cudaGetSymbolAddress(&pvh, g_vhi);
    cudaGetSymbolAddress(&pvl, g_vlo);
    cudaGetSymbolAddress(&pa,  g_attn);

    cudaFuncSetAttribute(flash_attn_bf16,
                         cudaFuncAttributeMaxDynamicSharedMemorySize, FA_SMEM);
    // Force max carveout (228KB) so TWO 92KB CTAs fit per SM. Without this the
    // driver picks the smallest bucket (100KB) that fits one CTA -> occ 12.4%.
    cudaFuncSetAttribute(flash_attn_bf16,
                         cudaFuncAttributePreferredSharedMemoryCarveout, 100);

    const dim3 gg(EMBED / GBN, M_TOT / GBM);   // (8, 64)
    const float qscale = 0.125f;               // 1/sqrt(HEAD_DIM)

    sgemm_tf32<0><<<gg, 256>>>(query,  Wq, bq, (u32*)pqh, (u32*)pql, nullptr, qscale);
    sgemm_tf32<0><<<gg, 256>>>(key_in, Wk, bk, (u32*)pkh, (u32*)pkl, nullptr, 1.0f);
    sgemm_tf32<0><<<gg, 256>>>(value,  Wv, bv, (u32*)pvh, (u32*)pvl, nullptr, 1.0f);

    flash_attn_bf16<<<dim3(NQT/2, BH), 128, FA_SMEM>>>(
        (const u32*)pqh, (const u32*)pql, (const u32*)pkh, (const u32*)pkl,
        (const u32*)pvh, (const u32*)pvl, (float*)pa);

    sgemm_tf32<1><<<gg, 256>>>((const float*)pa, Wo, bo, nullptr, nullptr, out, 1.0f);
}

// round 17
// speedup vs baseline: 1.5546x; 1.0607x over previous
#include <cuda_runtime.h>

#define EMBED    1024
#define HEADS    16
#define HEAD_DIM 64
#define BATCH    4
#define SEQ      2048
#define M_TOT    (BATCH*SEQ)      // 8192 rows
#define BH       (BATCH*HEADS)    // 64 batch-heads
#define NQT      (SEQ/64)         // 32 q-tiles per bh

typedef unsigned long long u64;
typedef unsigned int u32;

// ---------------- tf32 helpers (GEMM) ---------------------------------------
__device__ __forceinline__ u32 f2tf32(float x) {
    u32 r; asm("cvt.rna.tf32.f32 %0, %1;" : "=r"(r) : "f"(x)); return r;
}
__device__ __forceinline__ void mma_tf32(float* d, const u32* a, const u32* b) {
    asm volatile(
        "mma.sync.aligned.m16n8k8.row.col.f32.tf32.tf32.f32 "
        "{%0,%1,%2,%3}, {%4,%5,%6,%7}, {%8,%9}, {%0,%1,%2,%3};"
        : "+f"(d[0]), "+f"(d[1]), "+f"(d[2]), "+f"(d[3])
        : "r"(a[0]), "r"(a[1]), "r"(a[2]), "r"(a[3]), "r"(b[0]), "r"(b[1]));
}
__device__ __forceinline__ void cpa16(void* sdst, const void* gsrc) {
    u32 s = (u32)__cvta_generic_to_shared(sdst);
    asm volatile("cp.async.ca.shared.global [%0], [%1], 16;" :: "r"(s), "l"(gsrc));
}

// ---------------- bf16 / ldmatrix / mma helpers (flash) ---------------------
// word = {hi:bf16(vhi) | lo:bf16(vlo)}: PTX cvt first source -> upper half.
__device__ __forceinline__ u32 bfpack(float vhi, float vlo) {
    u32 r; asm("cvt.rn.bf16x2.f32 %0, %1, %2;" : "=r"(r) : "f"(vhi), "f"(vlo)); return r;
}
__device__ __forceinline__ void ldm_x4(u32* r, u32 saddr) {
    asm volatile("ldmatrix.sync.aligned.m8n8.x4.shared.b16 {%0,%1,%2,%3}, [%4];"
        : "=r"(r[0]), "=r"(r[1]), "=r"(r[2]), "=r"(r[3]) : "r"(saddr));
}
__device__ __forceinline__ void ldm_x4t(u32* r, u32 saddr) {
    asm volatile("ldmatrix.sync.aligned.m8n8.x4.trans.shared.b16 {%0,%1,%2,%3}, [%4];"
        : "=r"(r[0]), "=r"(r[1]), "=r"(r[2]), "=r"(r[3]) : "r"(saddr));
}
__device__ __forceinline__ void mma_bf16(float* d, const u32* a, const u32* b) {
    asm volatile(
        "mma.sync.aligned.m16n8k16.row.col.f32.bf16.bf16.f32 "
        "{%0,%1,%2,%3}, {%4,%5,%6,%7}, {%8,%9}, {%0,%1,%2,%3};"
        : "+f"(d[0]), "+f"(d[1]), "+f"(d[2]), "+f"(d[3])
        : "r"(a[0]), "r"(a[1]), "r"(a[2]), "r"(a[3]), "r"(b[0]), "r"(b[1]));
}

// ---------------- scratch (device globals: allocation-free) ----------------
// Q/K/V pre-split bf16 (hi,lo): u32 word = bf16x2 of adjacent dims {d+1|d}.
__device__ u32 g_qhi[BH * SEQ * 32];
__device__ u32 g_qlo[BH * SEQ * 32];
__device__ u32 g_khi[BH * SEQ * 32];
__device__ u32 g_klo[BH * SEQ * 32];
__device__ u32 g_vhi[BH * SEQ * 32];
__device__ u32 g_vlo[BH * SEQ * 32];
__device__ float g_attn[M_TOT * EMBED];        // [b,s,e]

// ---------------- tf32 tensor-core GEMM-NT (unchanged) ----------------------
#define GBM 128
#define GBN 128
#define GBK 16
#define GP  20
#define GNT (EMBED / GBK)

template<int MODE>
__global__ __launch_bounds__(256, 2) void sgemm_tf32(
    const float* __restrict__ A, const float* __restrict__ W,
    const float* __restrict__ bias,
    u32* __restrict__ Chi, u32* __restrict__ Clo,
    float* __restrict__ Cf, float scale)
{
    __shared__ float As[2][GBM][GP];
    __shared__ float Bs[2][GBN][GP];

    const int tid  = threadIdx.x;
    const int wid  = tid >> 5;
    const int lane = tid & 31;
    const int g    = lane >> 2;
    const int t4   = lane & 3;
    const int wm   = wid >> 2;
    const int wn   = wid & 3;
    const int m_base = wm * 64;
    const int n_base = wn * 32;

    const int row_blk = blockIdx.y * GBM;
    const int col_blk = blockIdx.x * GBN;

    const float* Ag = A + (size_t)row_blk * EMBED;
    const float* Bg = W + (size_t)col_blk * EMBED;

    const int cr = tid >> 2;
    const int cc = (tid & 3) * 4;

    float acc[4][4][4];
    #pragma unroll
    for (int mt = 0; mt < 4; mt++)
        #pragma unroll
        for (int nt = 0; nt < 4; nt++)
            #pragma unroll
            for (int r = 0; r < 4; r++) acc[mt][nt][r] = 0.f;

    {
        const float* ap = Ag + (size_t)cr * EMBED + cc;
        const float* bp = Bg + (size_t)cr * EMBED + cc;
        cpa16(&As[0][cr][cc],      ap);
        cpa16(&As[0][cr + 64][cc], ap + (size_t)64 * EMBED);
        cpa16(&Bs[0][cr][cc],      bp);
        cpa16(&Bs[0][cr + 64][cc], bp + (size_t)64 * EMBED);
        asm volatile("cp.async.commit_group;" ::: "memory");
    }

    for (int t = 0; t < GNT; t++) {
        const int s = t & 1;
        if (t + 1 < GNT) {
            const int sn = (t + 1) & 1;
            const float* ap = Ag + (size_t)cr * EMBED + (t + 1) * GBK + cc;
            const float* bp = Bg + (size_t)cr * EMBED + (t + 1) * GBK + cc;
            cpa16(&As[sn][cr][cc],      ap);
            cpa16(&As[sn][cr + 64][cc], ap + (size_t)64 * EMBED);
            cpa16(&Bs[sn][cr][cc],      bp);
            cpa16(&Bs[sn][cr + 64][cc], bp + (size_t)64 * EMBED);
            asm volatile("cp.async.commit_group;" ::: "memory");
            asm volatile("cp.async.wait_group 1;" ::: "memory");
        } else {
            asm volatile("cp.async.wait_group 0;" ::: "memory");
        }
        __syncthreads();

        #pragma unroll
        for (int kk = 0; kk < GBK; kk += 8) {
            u32 a[4][4], b[4][2];
            #pragma unroll
            for (int mt = 0; mt < 4; mt++) {
                const float* p = &As[s][m_base + mt*16 + g][kk + t4];
                a[mt][0] = f2tf32(p[0]);
                a[mt][1] = f2tf32(p[8 * GP]);
                a[mt][2] = f2tf32(p[4]);
                a[mt][3] = f2tf32(p[8 * GP + 4]);
            }
            #pragma unroll
            for (int nt = 0; nt < 4; nt++) {
                const float* p = &Bs[s][n_base + nt*8 + g][kk + t4];
                b[nt][0] = f2tf32(p[0]);
                b[nt][1] = f2tf32(p[4]);
            }
            #pragma unroll
            for (int mt = 0; mt < 4; mt++)
                #pragma unroll
                for (int nt = 0; nt < 4; nt++)
                    mma_tf32(acc[mt][nt], a[mt], b[nt]);
        }
        __syncthreads();
    }

    #pragma unroll
    for (int mt = 0; mt < 4; mt++) {
        #pragma unroll
        for (int nt = 0; nt < 4; nt++) {
            const int c0 = col_blk + n_base + nt*8 + 2*t4;   // even
            const float bia0 = bias[c0], bia1 = bias[c0 + 1];
            #pragma unroll
            for (int half = 0; half < 2; half++) {
                const int r = row_blk + m_base + mt*16 + g + half*8;
                float v0 = acc[mt][nt][half*2 + 0] + bia0;
                float v1 = acc[mt][nt][half*2 + 1] + bia1;
                if (MODE == 0) {
                    v0 *= scale; v1 *= scale;
                    u32 hp = bfpack(v1, v0);
                    float h0 = __uint_as_float(hp << 16);
                    float h1 = __uint_as_float(hp & 0xffff0000u);
                    u32 lp = bfpack(v1 - h1, v0 - h0);
                    const int bb = r / SEQ, ss = r % SEQ;
                    const int hh = c0 / HEAD_DIM, d = c0 % HEAD_DIM;
                    const size_t idx = (((size_t)(bb*HEADS + hh))*SEQ + ss)*32 + (d >> 1);
                    Chi[idx] = hp;
                    Clo[idx] = lp;
                } else {
                    *(float2*)&Cf[(size_t)r * EMBED + c0] = make_float2(v0, v1);
                }
            }
        }
    }
}

// ---------------- bf16 split-2 tensor-core flash attention ------------------
// Br=Bc=64, D=64. CTA = 128 thr (4 warps); warp w owns q-rows 16w..16w+15.
// m16n8k16 bf16; 3-term split (hh + hl + lh). P fragments stay in registers.
// K hi/lo: 2-stage cp.async ring. V hi/lo: SINGLE buffer, prefetched at tile
// start (V(kt) only needed after softmax(kt) -> latency hidden by S+softmax).
// smem 72KB/CTA -> 3 CTAs/SM (launch_bounds(128,3) caps regs at 170).
#define FPITCH 72                    // bf16 elems/row; 144B = conflict-free walk
#define TILE_B (64 * FPITCH * 2)     // 9216 B
#define SM_QH 0
#define SM_QL (1*TILE_B)
#define SM_K  (2*TILE_B)             // K ring base; stage s at SM_K + s*K_STAGE
#define K_STAGE (2*TILE_B)           // per stage: KH, KL
#define SM_V  (SM_K + 2*K_STAGE)     // VH, VL single buffer
#define FA_SMEM (SM_V + 2*TILE_B)    // 73728 B

__global__ __launch_bounds__(128, 3) void flash_attn_bf16(
    const u32* __restrict__ Qh, const u32* __restrict__ Ql,
    const u32* __restrict__ Kh, const u32* __restrict__ Kl,
    const u32* __restrict__ Vh, const u32* __restrict__ Vl,
    float* __restrict__ Out)
{
    extern __shared__ char smc[];
    const u32 smb = (u32)__cvta_generic_to_shared(smc);

    const int bh   = blockIdx.y;
    const int pair = blockIdx.x;
    const int tid  = threadIdx.x;
    const int wid  = tid >> 5;
    const int lane = tid & 31;
    const int g    = lane >> 2;
    const int t4   = lane & 3;
    const int b = bh / HEADS, h = bh % HEADS;

    // tile builders: thread -> (row 0..63, half 0..1), 4x16B per thread
    const int brow  = tid >> 1;
    const int bhalf = tid & 1;
    const u32 sm_row_off = (u32)(brow * 144 + bhalf * 64);
    const size_t g_row_off = (size_t)brow * 32 + bhalf * 16;

    // ldmatrix byte offsets (within a tile)
    const u32 a_off  = (u32)(((lane & 15) * FPITCH + ((lane >> 4) << 3)) * 2);
    const u32 kb_off = (u32)(((lane & 7) * FPITCH
                              + (((lane >> 3) & 1) << 3) + ((lane >> 4) << 4)) * 2);
    const u32 vb_off = (u32)(lane * FPITCH * 2);

    const size_t bh_base = (size_t)bh * SEQ * 32;

    // cp.async K hi/lo tiles for k-tile kt into ring stage s (own commit group)
    auto issue_k = [&](int kt, int s) {
        const size_t kbase = bh_base + (size_t)(kt*64)*32 + g_row_off;
        char* dst = smc + SM_K + s*K_STAGE;
        const u32* skh = Kh + kbase;  const u32* skl = Kl + kbase;
        #pragma unroll
        for (int i = 0; i < 4; i++) {
            cpa16(dst + 0*TILE_B + sm_row_off + i*16, skh + i*4);
            cpa16(dst + 1*TILE_B + sm_row_off + i*16, skl + i*4);
        }
        asm volatile("cp.async.commit_group;" ::: "memory");
    };
    // cp.async V hi/lo tiles for k-tile kt into the single V buffer
    auto issue_v = [&](int kt) {
        const size_t kbase = bh_base + (size_t)(kt*64)*32 + g_row_off;
        char* dst = smc + SM_V;
        const u32* svh = Vh + kbase;  const u32* svl = Vl + kbase;
        #pragma unroll
        for (int i = 0; i < 4; i++) {
            cpa16(dst + 0*TILE_B + sm_row_off + i*16, svh + i*4);
            cpa16(dst + 1*TILE_B + sm_row_off + i*16, svl + i*4);
        }
        asm volatile("cp.async.commit_group;" ::: "memory");
    };

    #pragma unroll 1
    for (int pass = 0; pass < 2; pass++) {
        const int qt = pass ? pair : (NQT - 1 - pair);   // long tile first
        const int q0 = qt * 64;

        __syncthreads();   // all buffers free from previous pass readers

        // build Q hi/lo tiles (sync stores) + kick off K(0)
        {
            const u32* sqh = Qh + bh_base + (size_t)q0*32 + g_row_off;
            const u32* sql = Ql + bh_base + (size_t)q0*32 + g_row_off;
            #pragma unroll
            for (int i = 0; i < 4; i++) {
                *(uint4*)(smc + SM_QH + sm_row_off + i*16) = *(const uint4*)(sqh + i*4);
                *(uint4*)(smc + SM_QL + sm_row_off + i*16) = *(const uint4*)(sql + i*4);
            }
        }
        issue_k(0, 0);
        __syncthreads();   // Q tile visible

        // Q fragments (registers, reused across k-tiles)
        u32 qfh[4][4], qfl[4][4];
        #pragma unroll
        for (int kc = 0; kc < 4; kc++) {
            const u32 off = (u32)(wid*16*144) + a_off + kc*32;
            ldm_x4(qfh[kc], smb + SM_QH + off);
            ldm_x4(qfl[kc], smb + SM_QL + off);
        }

        float m0 = -1e30f, m1 = -1e30f, l0 = 0.f, l1 = 0.f;
        float o[8][4];
        #pragma unroll
        for (int nt = 0; nt < 8; nt++)
            #pragma unroll
            for (int e = 0; e < 4; e++) o[nt][e] = 0.f;

        for (int kt = 0; kt <= qt; kt++) {
            const int s = kt & 1;
            // drain everything pending: K(kt) has arrived (V(kt-1) drained
            // before PV last iter).
            asm volatile("cp.async.wait_group 0;" ::: "memory");
            __syncthreads();   // K(kt) visible; stage s^1 + Vbuf reads all done
            // prefetch V(kt) (needed post-softmax) and K(kt+1) (needed next tile)
            issue_v(kt);
            if (kt < qt) issue_k(kt + 1, s ^ 1);

            const u32 kh_b = smb + SM_K + (u32)(s * K_STAGE);
            const u32 kl_b = kh_b + TILE_B;
            const u32 vh_b = smb + SM_V;
            const u32 vl_b = vh_b + TILE_B;

            // ---- S = Q K^T (3-term split) ----
            float sacc[8][4];
            #pragma unroll
            for (int nt = 0; nt < 8; nt++)
                #pragma unroll
                for (int e = 0; e < 4; e++) sacc[nt][e] = 0.f;

            #pragma unroll
            for (int nt = 0; nt < 8; nt++) {
                #pragma unroll
                for (int kcp = 0; kcp < 2; kcp++) {       // k32 double-chunks
                    const u32 off = (u32)(nt*8*144) + kb_off + kcp*64;
                    u32 kbh[4], kbl[4];
                    ldm_x4(kbh, kh_b + off);
                    ldm_x4(kbl, kl_b + off);
                    mma_bf16(sacc[nt], qfh[2*kcp],   kbh);
                    mma_bf16(sacc[nt], qfh[2*kcp],   kbl);
                    mma_bf16(sacc[nt], qfl[2*kcp],   kbh);
                    mma_bf16(sacc[nt], qfh[2*kcp+1], kbh + 2);
                    mma_bf16(sacc[nt], qfh[2*kcp+1], kbl + 2);
                    mma_bf16(sacc[nt], qfl[2*kcp+1], kbh + 2);
                }
            }

            // ---- causal mask (diagonal tile; local coords) ----
            if (kt == qt) {
                const int row0 = wid*16 + g;
                #pragma unroll
                for (int nt = 0; nt < 8; nt++) {
                    const int c0l = nt*8 + 2*t4;
                    if (c0l     > row0)     sacc[nt][0] = -1e30f;
                    if (c0l + 1 > row0)     sacc[nt][1] = -1e30f;
                    if (c0l     > row0 + 8) sacc[nt][2] = -1e30f;
                    if (c0l + 1 > row0 + 8) sacc[nt][3] = -1e30f;
                }
            }

            // ---- online softmax (rows g and g+8; quad shfl over t4) ----
            float mx0 = -1e30f, mx1 = -1e30f;
            #pragma unroll
            for (int nt = 0; nt < 8; nt++) {
                mx0 = fmaxf(mx0, fmaxf(sacc[nt][0], sacc[nt][1]));
                mx1 = fmaxf(mx1, fmaxf(sacc[nt][2], sacc[nt][3]));
            }
            mx0 = fmaxf(mx0, __shfl_xor_sync(0xffffffffu, mx0, 1));
            mx0 = fmaxf(mx0, __shfl_xor_sync(0xffffffffu, mx0, 2));
            mx1 = fmaxf(mx1, __shfl_xor_sync(0xffffffffu, mx1, 1));
            mx1 = fmaxf(mx1, __shfl_xor_sync(0xffffffffu, mx1, 2));
            const float mn0 = fmaxf(m0, mx0), mn1 = fmaxf(m1, mx1);
            const float al0 = __expf(m0 - mn0), al1 = __expf(m1 - mn1);

            u32 phi[8], plo[8], phi2[8], plo2[8];
            float sum0 = 0.f, sum1 = 0.f;
            #pragma unroll
            for (int nt = 0; nt < 8; nt++) {
                const float p00 = __expf(sacc[nt][0] - mn0);
                const float p01 = __expf(sacc[nt][1] - mn0);
                const float p10 = __expf(sacc[nt][2] - mn1);
                const float p11 = __expf(sacc[nt][3] - mn1);
                sum0 += p00 + p01;
                sum1 += p10 + p11;
                const u32 hp0 = bfpack(p01, p00);
                phi[nt] = hp0;
                plo[nt] = bfpack(p01 - __uint_as_float(hp0 & 0xffff0000u),
                                 p00 - __uint_as_float(hp0 << 16));
                const u32 hp1 = bfpack(p11, p10);
                phi2[nt] = hp1;
                plo2[nt] = bfpack(p11 - __uint_as_float(hp1 & 0xffff0000u),
                                  p10 - __uint_as_float(hp1 << 16));
            }
            sum0 += __shfl_xor_sync(0xffffffffu, sum0, 1);
            sum0 += __shfl_xor_sync(0xffffffffu, sum0, 2);
            sum1 += __shfl_xor_sync(0xffffffffu, sum1, 1);
            sum1 += __shfl_xor_sync(0xffffffffu, sum1, 2);
            l0 = l0 * al0 + sum0;
            l1 = l1 * al1 + sum1;
            m0 = mn0; m1 = mn1;
            #pragma unroll
            for (int nt = 0; nt < 8; nt++) {
                o[nt][0] *= al0; o[nt][1] *= al0;
                o[nt][2] *= al1; o[nt][3] *= al1;
            }

            // ---- drain V(kt) (keep K(kt+1) in flight), make visible ----
            if (kt < qt) {
                asm volatile("cp.async.wait_group 1;" ::: "memory");
            } else {
                asm volatile("cp.async.wait_group 0;" ::: "memory");
            }
            __syncthreads();

            // ---- O += P V (3-term split; P A-fragments from registers) ----
            #pragma unroll
            for (int nt = 0; nt < 8; nt++) {          // d tiles of 8
                #pragma unroll
                for (int kcp = 0; kcp < 2; kcp++) {   // c32 double-chunks
                    const u32 off = (u32)(kcp*32*144) + vb_off + nt*16;
                    u32 vbh[4], vbl[4];
                    ldm_x4t(vbh, vh_b + off);
                    ldm_x4t(vbl, vl_b + off);
                    const int kc0 = 2*kcp, kc1 = 2*kcp + 1;
                    u32 pah0[4] = {phi[2*kc0], phi2[2*kc0], phi[2*kc0+1], phi2[2*kc0+1]};
                    u32 pal0[4] = {plo[2*kc0], plo2[2*kc0], plo[2*kc0+1], plo2[2*kc0+1]};
                    mma_bf16(o[nt], pah0, vbh);
                    mma_bf16(o[nt], pah0, vbl);
                    mma_bf16(o[nt], pal0, vbh);
                    u32 pah1[4] = {phi[2*kc1], phi2[2*kc1], phi[2*kc1+1], phi2[2*kc1+1]};
                    u32 pal1[4] = {plo[2*kc1], plo2[2*kc1], plo[2*kc1+1], plo2[2*kc1+1]};
                    mma_bf16(o[nt], pah1, vbh + 2);
                    mma_bf16(o[nt], pah1, vbl + 2);
                    mma_bf16(o[nt], pal1, vbh + 2);
                }
            }
        }

        // ---- writeback: Out[b, q0+row, h*64 + d] ----
        const float i0 = 1.0f / l0, i1 = 1.0f / l1;
        const int r0 = q0 + wid*16 + g;
        #pragma unroll
        for (int nt = 0; nt < 8; nt++) {
            const int d = nt*8 + 2*t4;
            *(float2*)&Out[((size_t)(b*SEQ + r0    ))*EMBED + h*HEAD_DIM + d] =
                make_float2(o[nt][0]*i0, o[nt][1]*i0);
            *(float2*)&Out[((size_t)(b*SEQ + r0 + 8))*EMBED + h*HEAD_DIM + d] =
                make_float2(o[nt][2]*i1, o[nt][3]*i1);
        }
    }
}

// ---------------------------------------------------------------------------
extern "C" void kernel_launch(void* const* d_in, const int* in_sizes, int n_in,
                              void* d_out, int out_size)
{
    const float* query  = (const float*)d_in[0];
    const float* key_in = (const float*)d_in[1];
    const float* value  = (const float*)d_in[2];
    // d_in[3] = causal mask (int32), known causal -> unused
    const float* Wq = (const float*)d_in[4];
    const float* bq = (const float*)d_in[5];
    const float* Wk = (const float*)d_in[6];
    const float* bk = (const float*)d_in[7];
    const float* Wv = (const float*)d_in[8];
    const float* bv = (const float*)d_in[9];
    const float* Wo = (const float*)d_in[10];
    const float* bo = (const float*)d_in[11];
    float* out = (float*)d_out;

    void *pqh, *pql, *pkh, *pkl, *pvh, *pvl, *pa;
    cudaGetSymbolAddress(&pqh, g_qhi);
    cudaGetSymbolAddress(&pql, g_qlo);
    cudaGetSymbolAddress(&pkh, g_khi);
    cudaGetSymbolAddress(&pkl, g_klo);
    cudaGetSymbolAddress(&pvh, g_vhi);
    cudaGetSymbolAddress(&pvl, g_vlo);
    cudaGetSymbolAddress(&pa,  g_attn);

    cudaFuncSetAttribute(flash_attn_bf16,
                         cudaFuncAttributeMaxDynamicSharedMemorySize, FA_SMEM);
    cudaFuncSetAttribute(flash_attn_bf16,
                         cudaFuncAttributePreferredSharedMemoryCarveout, 100);

    const dim3 gg(EMBED / GBN, M_TOT / GBM);   // (8, 64)
    const float qscale = 0.125f;               // 1/sqrt(HEAD_DIM)

    sgemm_tf32<0><<<gg, 256>>>(query,  Wq, bq, (u32*)pqh, (u32*)pql, nullptr, qscale);
    sgemm_tf32<0><<<gg, 256>>>(key_in, Wk, bk, (u32*)pkh, (u32*)pkl, nullptr, 1.0f);
    sgemm_tf32<0><<<gg, 256>>>(value,  Wv, bv, (u32*)pvh, (u32*)pvl, nullptr, 1.0f);

    flash_attn_bf16<<<dim3(NQT/2, BH), 128, FA_SMEM>>>(
        (const u32*)pqh, (const u32*)pql, (const u32*)pkh, (const u32*)pkl,
        (const u32*)pvh, (const u32*)pvl, (float*)pa);

    sgemm_tf32<1><<<gg, 256>>>((const float*)pa, Wo, bo, nullptr, nullptr, out, 1.0f);
}